// round 1
// baseline (speedup 1.0000x reference)
#include <cuda_runtime.h>
#include <math.h>

// Problem constants
#define BATCH 4
#define SEQ   2048
#define DIM   1024
#define NHEAD 16
#define HDIM  64
#define WIN   256

// Scratch (device globals: allocation-free rule)
__device__ float g_q[BATCH * SEQ * DIM];
__device__ float g_k[BATCH * SEQ * DIM];
__device__ float g_v[BATCH * SEQ * DIM];
__device__ float g_ctx[BATCH * SEQ * DIM];

// ---------------------------------------------------------------------------
// SGEMM NT: C[M,N] = A[M,K] @ W[N,K]^T (+ bias). 128x128 block, 8x8/thread.
// ---------------------------------------------------------------------------
template <bool HAS_BIAS>
__global__ __launch_bounds__(256) void sgemm_nt(const float* __restrict__ A,
                                                const float* __restrict__ W,
                                                const float* __restrict__ bias,
                                                float* __restrict__ C,
                                                int M, int N, int K) {
    const int BM = 128, BN = 128, BK = 16;
    __shared__ float As[BK][BM + 4];
    __shared__ float Bs[BK][BN + 4];

    int tid = threadIdx.x;
    int bm = blockIdx.y * BM;
    int bn = blockIdx.x * BN;

    int lr = tid >> 2;          // 0..63   (row within 64-row load group)
    int lc = (tid & 3) << 2;    // 0,4,8,12 (k offset, float4)

    int trow = (tid >> 4) << 3; // 0..120 step 8
    int tcol = (tid & 15) << 3; // 0..120 step 8

    float acc[8][8];
#pragma unroll
    for (int i = 0; i < 8; i++)
#pragma unroll
        for (int j = 0; j < 8; j++) acc[i][j] = 0.0f;

    const float* Ap = A + (size_t)bm * K;
    const float* Wp = W + (size_t)bn * K;

    for (int k0 = 0; k0 < K; k0 += BK) {
#pragma unroll
        for (int p = 0; p < 2; p++) {
            int r = lr + p * 64;
            float4 va = *(const float4*)(Ap + (size_t)r * K + k0 + lc);
            As[lc + 0][r] = va.x;
            As[lc + 1][r] = va.y;
            As[lc + 2][r] = va.z;
            As[lc + 3][r] = va.w;
            float4 vb = *(const float4*)(Wp + (size_t)r * K + k0 + lc);
            Bs[lc + 0][r] = vb.x;
            Bs[lc + 1][r] = vb.y;
            Bs[lc + 2][r] = vb.z;
            Bs[lc + 3][r] = vb.w;
        }
        __syncthreads();

#pragma unroll
        for (int kk = 0; kk < BK; kk++) {
            float ra[8], rb[8];
#pragma unroll
            for (int i = 0; i < 8; i++) ra[i] = As[kk][trow + i];
#pragma unroll
            for (int j = 0; j < 8; j++) rb[j] = Bs[kk][tcol + j];
#pragma unroll
            for (int i = 0; i < 8; i++)
#pragma unroll
                for (int j = 0; j < 8; j++) acc[i][j] += ra[i] * rb[j];
        }
        __syncthreads();
    }

#pragma unroll
    for (int i = 0; i < 8; i++) {
        float* Crow = C + (size_t)(bm + trow + i) * N + bn + tcol;
#pragma unroll
        for (int j = 0; j < 8; j += 4) {
            float4 o;
            o.x = acc[i][j + 0];
            o.y = acc[i][j + 1];
            o.z = acc[i][j + 2];
            o.w = acc[i][j + 3];
            if (HAS_BIAS) {
                o.x += bias[bn + tcol + j + 0];
                o.y += bias[bn + tcol + j + 1];
                o.z += bias[bn + tcol + j + 2];
                o.w += bias[bn + tcol + j + 3];
            }
            *(float4*)(Crow + j) = o;
        }
    }
}

// ---------------------------------------------------------------------------
// Windowed causal flash attention.
// Grid: (SEQ/BQ, NHEAD, BATCH). Block: 256 threads (8 warps, 4 query rows each).
// Online softmax over key tiles of 32 within [qb-255, qb+31].
// ---------------------------------------------------------------------------
#define BQ 32

__global__ __launch_bounds__(256) void attn_kernel(const float* __restrict__ Q,
                                                   const float* __restrict__ K,
                                                   const float* __restrict__ V,
                                                   float* __restrict__ O) {
    __shared__ float Qs[BQ][HDIM];       // broadcast reads
    __shared__ float Ks[BQ][HDIM + 1];   // pad: conflict-free row reads
    __shared__ float Vs[BQ][HDIM + 1];
    __shared__ float Ps[BQ][BQ + 1];     // per-tile probabilities

    int qb = blockIdx.x * BQ;
    int h = blockIdx.y;
    int b = blockIdx.z;
    int tid = threadIdx.x;
    int warp = tid >> 5;
    int lane = tid & 31;

    const size_t headbase = ((size_t)b * SEQ) * DIM + (size_t)h * HDIM;
    const float* Qb = Q + headbase + (size_t)qb * DIM;

    // load Q tile: 32 rows x 64 floats = 512 float4
    for (int i = tid; i < BQ * (HDIM / 4); i += 256) {
        int q = i >> 4;
        int d4 = (i & 15) << 2;
        *(float4*)&Qs[q][d4] = *(const float4*)(Qb + (size_t)q * DIM + d4);
    }

    int kstart = qb - (WIN - 1);
    if (kstart < 0) kstart = 0;
    int kend = qb + BQ - 1;

    float m[4], l[4], acc0[4], acc1[4];
#pragma unroll
    for (int i = 0; i < 4; i++) {
        m[i] = -1e30f;
        l[i] = 0.0f;
        acc0[i] = 0.0f;
        acc1[i] = 0.0f;
    }

    for (int kt = kstart; kt <= kend; kt += BQ) {
        int ktn = kend + 1 - kt;
        if (ktn > BQ) ktn = BQ;

        __syncthreads();  // protect Ks/Vs from previous iteration; covers Qs on iter 0

        const float* Kb = K + headbase + (size_t)kt * DIM;
        const float* Vb = V + headbase + (size_t)kt * DIM;
        for (int i = tid; i < ktn * (HDIM / 4); i += 256) {
            int r = i >> 4;
            int d4 = (i & 15) << 2;
            float4 kv = *(const float4*)(Kb + (size_t)r * DIM + d4);
            Ks[r][d4 + 0] = kv.x;
            Ks[r][d4 + 1] = kv.y;
            Ks[r][d4 + 2] = kv.z;
            Ks[r][d4 + 3] = kv.w;
            float4 vv = *(const float4*)(Vb + (size_t)r * DIM + d4);
            Vs[r][d4 + 0] = vv.x;
            Vs[r][d4 + 1] = vv.y;
            Vs[r][d4 + 2] = vv.z;
            Vs[r][d4 + 3] = vv.w;
        }
        __syncthreads();

        // --- scores + online softmax update (lane = key) ---
#pragma unroll
        for (int qq = 0; qq < 4; qq++) {
            int q = warp * 4 + qq;
            int qi = qb + q;
            int j = kt + lane;
            bool valid = (lane < ktn) && (j <= qi) && (qi - j < WIN);
            float s = -1e30f;
            if (valid) {
                s = 0.0f;
#pragma unroll
                for (int d = 0; d < HDIM; d++) s += Qs[q][d] * Ks[lane][d];
            }
            float tm = s;
#pragma unroll
            for (int off = 16; off; off >>= 1)
                tm = fmaxf(tm, __shfl_xor_sync(0xffffffffu, tm, off));
            float mnew = fmaxf(m[qq], tm);
            float p = valid ? __expf(s - mnew) : 0.0f;
            Ps[q][lane] = p;
            float ps = p;
#pragma unroll
            for (int off = 16; off; off >>= 1)
                ps += __shfl_xor_sync(0xffffffffu, ps, off);
            float corr = __expf(m[qq] - mnew);
            l[qq] = l[qq] * corr + ps;
            m[qq] = mnew;
            acc0[qq] *= corr;
            acc1[qq] *= corr;
        }
        __syncwarp();

        // --- P @ V (lane = head dim) ---
#pragma unroll
        for (int qq = 0; qq < 4; qq++) {
            int q = warp * 4 + qq;
            for (int k2 = 0; k2 < ktn; k2++) {
                float p = Ps[q][k2];
                acc0[qq] += p * Vs[k2][lane];
                acc1[qq] += p * Vs[k2][lane + 32];
            }
        }
    }

    float* Ob = O + headbase + (size_t)qb * DIM;
#pragma unroll
    for (int qq = 0; qq < 4; qq++) {
        int q = warp * 4 + qq;
        float inv = 1.0f / l[qq];
        Ob[(size_t)q * DIM + lane] = acc0[qq] * inv;
        Ob[(size_t)q * DIM + lane + 32] = acc1[qq] * inv;
    }
}

// ---------------------------------------------------------------------------
extern "C" void kernel_launch(void* const* d_in, const int* in_sizes, int n_in,
                              void* d_out, int out_size) {
    (void)in_sizes; (void)n_in; (void)out_size;
    const float* X  = (const float*)d_in[0];
    const float* Wq = (const float*)d_in[1];
    const float* Wk = (const float*)d_in[2];
    const float* Wv = (const float*)d_in[3];
    const float* Wo = (const float*)d_in[4];
    const float* bo = (const float*)d_in[5];
    float* out = (float*)d_out;

    float *q, *k, *v, *ctx;
    cudaGetSymbolAddress((void**)&q, g_q);
    cudaGetSymbolAddress((void**)&k, g_k);
    cudaGetSymbolAddress((void**)&v, g_v);
    cudaGetSymbolAddress((void**)&ctx, g_ctx);

    const int M = BATCH * SEQ;   // 8192
    const int N = DIM;           // 1024
    const int Kd = DIM;          // 1024

    dim3 gemm_grid(N / 128, M / 128);
    sgemm_nt<false><<<gemm_grid, 256>>>(X, Wq, nullptr, q, M, N, Kd);
    sgemm_nt<false><<<gemm_grid, 256>>>(X, Wk, nullptr, k, M, N, Kd);
    sgemm_nt<false><<<gemm_grid, 256>>>(X, Wv, nullptr, v, M, N, Kd);

    dim3 attn_grid(SEQ / BQ, NHEAD, BATCH);
    attn_kernel<<<attn_grid, 256>>>(q, k, v, ctx);

    sgemm_nt<true><<<gemm_grid, 256>>>(ctx, Wo, bo, out, M, N, Kd);
}

// round 3
// speedup vs baseline: 2.4154x; 2.4154x over previous
#include <cuda_runtime.h>
#include <cuda_bf16.h>
#include <stdint.h>

// Problem constants
#define BATCH 4
#define SEQ   2048
#define DIM   1024
#define NHEAD 16
#define HDIM  64
#define WIN   256
#define MROWS (BATCH * SEQ)   // 8192

// ---------------------------------------------------------------------------
// Scratch (device globals: allocation-free rule)
// ---------------------------------------------------------------------------
__device__ float g_q[MROWS * DIM];
__device__ float g_k[MROWS * DIM];
__device__ float g_v[MROWS * DIM];
__device__ float g_ctx[MROWS * DIM];
__device__ __nv_bfloat16 g_xh[MROWS * DIM];
__device__ __nv_bfloat16 g_xl[MROWS * DIM];
__device__ __nv_bfloat16 g_ch[MROWS * DIM];
__device__ __nv_bfloat16 g_cl[MROWS * DIM];
__device__ __nv_bfloat16 g_wqh[DIM * DIM];
__device__ __nv_bfloat16 g_wql[DIM * DIM];
__device__ __nv_bfloat16 g_wkh[DIM * DIM];
__device__ __nv_bfloat16 g_wkl[DIM * DIM];
__device__ __nv_bfloat16 g_wvh[DIM * DIM];
__device__ __nv_bfloat16 g_wvl[DIM * DIM];
__device__ __nv_bfloat16 g_woh[DIM * DIM];
__device__ __nv_bfloat16 g_wol[DIM * DIM];

// ---------------------------------------------------------------------------
// Portable PTX helpers (no arch-specific features)
// ---------------------------------------------------------------------------
__device__ __forceinline__ uint32_t smem_u32(const void* p) {
    uint32_t a;
    asm("{ .reg .u64 t; cvta.to.shared.u64 t, %1; cvt.u32.u64 %0, t; }"
        : "=r"(a) : "l"(p));
    return a;
}

#define CP_ASYNC16(dst, src) \
    asm volatile("cp.async.cg.shared.global [%0], [%1], 16;" :: "r"(dst), "l"(src))
#define CP_COMMIT() asm volatile("cp.async.commit_group;" ::: "memory")
#define CP_WAIT(n)  asm volatile("cp.async.wait_group %0;" :: "n"(n) : "memory")

__device__ __forceinline__ void ldsm_x4(uint32_t& r0, uint32_t& r1,
                                        uint32_t& r2, uint32_t& r3, uint32_t addr) {
    asm volatile("ldmatrix.sync.aligned.m8n8.x4.shared.b16 {%0,%1,%2,%3}, [%4];"
                 : "=r"(r0), "=r"(r1), "=r"(r2), "=r"(r3) : "r"(addr));
}

__device__ __forceinline__ void mma_bf16(float& c0, float& c1, float& c2, float& c3,
                                         uint32_t a0, uint32_t a1, uint32_t a2, uint32_t a3,
                                         uint32_t b0, uint32_t b1) {
    asm volatile(
        "mma.sync.aligned.m16n8k16.row.col.f32.bf16.bf16.f32 "
        "{%0,%1,%2,%3}, {%4,%5,%6,%7}, {%8,%9}, {%0,%1,%2,%3};"
        : "+f"(c0), "+f"(c1), "+f"(c2), "+f"(c3)
        : "r"(a0), "r"(a1), "r"(a2), "r"(a3), "r"(b0), "r"(b1));
}

// ---------------------------------------------------------------------------
// fp32 -> bf16 hi/lo split
// ---------------------------------------------------------------------------
__global__ __launch_bounds__(256) void split_bf16(const float* __restrict__ src,
                                                  __nv_bfloat16* __restrict__ hi,
                                                  __nv_bfloat16* __restrict__ lo,
                                                  int n) {
    int i = (blockIdx.x * 256 + threadIdx.x) * 4;
    if (i >= n) return;
    float4 x = *(const float4*)(src + i);
    __nv_bfloat16 h0 = __float2bfloat16(x.x);
    __nv_bfloat16 h1 = __float2bfloat16(x.y);
    __nv_bfloat16 h2 = __float2bfloat16(x.z);
    __nv_bfloat16 h3 = __float2bfloat16(x.w);
    __nv_bfloat16 l0 = __float2bfloat16(x.x - __bfloat162float(h0));
    __nv_bfloat16 l1 = __float2bfloat16(x.y - __bfloat162float(h1));
    __nv_bfloat16 l2 = __float2bfloat16(x.z - __bfloat162float(h2));
    __nv_bfloat16 l3 = __float2bfloat16(x.w - __bfloat162float(h3));
    __nv_bfloat162* ph = (__nv_bfloat162*)(hi + i);
    __nv_bfloat162* pl = (__nv_bfloat162*)(lo + i);
    ph[0] = __nv_bfloat162(h0, h1);
    ph[1] = __nv_bfloat162(h2, h3);
    pl[0] = __nv_bfloat162(l0, l1);
    pl[1] = __nv_bfloat162(l2, l3);
}

// ---------------------------------------------------------------------------
// HMMA bf16-split GEMM: C[M,N] = (Ah+Al)[M,K] @ (Bh+Bl)[N,K]^T (+ bias)
// 128x128 tile, BK=32, 8 warps (2m x 4n), warp tile 64x32, m16n8k16 atoms.
// 3 passes: Ah*Bh + Ah*Bl + Al*Bh.
// SMEM rows pitched to 80B (40 halves): conflict-free ldmatrix + aligned.
// ---------------------------------------------------------------------------
#define GP      40                 // smem pitch in bf16 elems (80 bytes)
#define TBYTES  (128 * GP * 2)     // 10240 bytes per operand tile
#define STAGEB  (4 * TBYTES)       // 40960 per stage
#define NCH     (DIM / 32)         // 32 K-chunks

template <bool HAS_BIAS>
__global__ __launch_bounds__(256) void gemm_mma(const __nv_bfloat16* __restrict__ Ah,
                                                const __nv_bfloat16* __restrict__ Al,
                                                const __nv_bfloat16* __restrict__ Bh,
                                                const __nv_bfloat16* __restrict__ Bl,
                                                const float* __restrict__ bias,
                                                float* __restrict__ C) {
    extern __shared__ char smem[];
    const int tid = threadIdx.x;
    const int wid = tid >> 5;
    const int lane = tid & 31;
    const int bm = blockIdx.y * 128;
    const int bn = blockIdx.x * 128;

    const int wm = (wid & 1) * 64;   // warp m offset
    const int wn = (wid >> 1) * 32;  // warp n offset

    const uint32_t sbase = smem_u32(smem);

    // global source row bases (bytes): A rows bm.., B rows bn..
    const char* gAh = (const char*)Ah + (size_t)bm * (DIM * 2);
    const char* gAl = (const char*)Al + (size_t)bm * (DIM * 2);
    const char* gBh = (const char*)Bh + (size_t)bn * (DIM * 2);
    const char* gBl = (const char*)Bl + (size_t)bn * (DIM * 2);

    // per-thread load slots: 512 16B-chunks per tensor, 2 per thread per tensor
    const int t0 = tid, t1 = tid + 256;

    auto issue = [&](int c, int s) {
        char* st = smem + s * STAGEB;
        const size_t gk = (size_t)c * 64;  // 32 bf16 = 64 bytes
#pragma unroll
        for (int rep = 0; rep < 2; rep++) {
            int t = rep ? t1 : t0;
            int r = t >> 2;
            int cc = (t & 3) << 4;
            uint32_t dst = smem_u32(st) + r * 80 + cc;
            size_t src = (size_t)r * (DIM * 2) + gk + cc;
            CP_ASYNC16(dst,              gAh + src);
            CP_ASYNC16(dst + TBYTES,     gAl + src);
            CP_ASYNC16(dst + 2 * TBYTES, gBh + src);
            CP_ASYNC16(dst + 3 * TBYTES, gBl + src);
        }
    };

    float acc[4][4][4];
#pragma unroll
    for (int i = 0; i < 4; i++)
#pragma unroll
        for (int j = 0; j < 4; j++)
#pragma unroll
            for (int r = 0; r < 4; r++) acc[i][j][r] = 0.0f;

    // ldmatrix lane address offsets (within a tile, bytes)
    // A 16x16 tile at (mrow, kk): row = mrow + (l&15), col halves = kk + (l>>4)*8
    const int a_r = lane & 15, a_c = (lane >> 4) * 8;
    // B 16(n)x16(k) tile at (nrow, kk): row = nrow + (l&7) + ((l>>4)&1)*8, col = kk + ((l>>3)&1)*8
    const int b_r = (lane & 7) + ((lane >> 4) & 1) * 8, b_c = ((lane >> 3) & 1) * 8;

    issue(0, 0);
    CP_COMMIT();

    for (int c = 0; c < NCH; ++c) {
        const int s = c & 1;
        if (c + 1 < NCH) {
            issue(c + 1, s ^ 1);
            CP_COMMIT();
            CP_WAIT(1);
        } else {
            CP_WAIT(0);
        }
        __syncthreads();

        const uint32_t st = sbase + s * STAGEB;
        const uint32_t pAh = st;
        const uint32_t pAl = st + TBYTES;
        const uint32_t pBh = st + 2 * TBYTES;
        const uint32_t pBl = st + 3 * TBYTES;

#pragma unroll
        for (int kk = 0; kk < 32; kk += 16) {
            uint32_t ah[4][4], al[4][4];
#pragma unroll
            for (int mi = 0; mi < 4; mi++) {
                uint32_t off = (uint32_t)((wm + mi * 16 + a_r) * 80 + (kk + a_c) * 2);
                ldsm_x4(ah[mi][0], ah[mi][1], ah[mi][2], ah[mi][3], pAh + off);
                ldsm_x4(al[mi][0], al[mi][1], al[mi][2], al[mi][3], pAl + off);
            }
            uint32_t bh[4][2], bl[4][2];
#pragma unroll
            for (int nb = 0; nb < 2; nb++) {
                uint32_t off = (uint32_t)((wn + nb * 16 + b_r) * 80 + (kk + b_c) * 2);
                uint32_t r0, r1, r2, r3;
                ldsm_x4(r0, r1, r2, r3, pBh + off);
                bh[nb * 2][0] = r0; bh[nb * 2][1] = r1;
                bh[nb * 2 + 1][0] = r2; bh[nb * 2 + 1][1] = r3;
                ldsm_x4(r0, r1, r2, r3, pBl + off);
                bl[nb * 2][0] = r0; bl[nb * 2][1] = r1;
                bl[nb * 2 + 1][0] = r2; bl[nb * 2 + 1][1] = r3;
            }
#pragma unroll
            for (int mi = 0; mi < 4; mi++)
#pragma unroll
                for (int ni = 0; ni < 4; ni++) {
                    mma_bf16(acc[mi][ni][0], acc[mi][ni][1], acc[mi][ni][2], acc[mi][ni][3],
                             ah[mi][0], ah[mi][1], ah[mi][2], ah[mi][3],
                             bh[ni][0], bh[ni][1]);
                    mma_bf16(acc[mi][ni][0], acc[mi][ni][1], acc[mi][ni][2], acc[mi][ni][3],
                             ah[mi][0], ah[mi][1], ah[mi][2], ah[mi][3],
                             bl[ni][0], bl[ni][1]);
                    mma_bf16(acc[mi][ni][0], acc[mi][ni][1], acc[mi][ni][2], acc[mi][ni][3],
                             al[mi][0], al[mi][1], al[mi][2], al[mi][3],
                             bh[ni][0], bh[ni][1]);
                }
        }
        __syncthreads();
    }

    // Epilogue: c-frag (row = lane/4 [+8], col = (lane%4)*2 [+1]) direct stores
    const int er = lane >> 2;
    const int ec = (lane & 3) * 2;
#pragma unroll
    for (int mi = 0; mi < 4; mi++) {
#pragma unroll
        for (int ni = 0; ni < 4; ni++) {
            int col = bn + wn + ni * 8 + ec;
            float b0 = 0.f, b1 = 0.f;
            if (HAS_BIAS) { b0 = bias[col]; b1 = bias[col + 1]; }
            float* p0 = C + (size_t)(bm + wm + mi * 16 + er) * DIM + col;
            float* p1 = C + (size_t)(bm + wm + mi * 16 + er + 8) * DIM + col;
            float2 v0 = make_float2(acc[mi][ni][0] + b0, acc[mi][ni][1] + b1);
            float2 v1 = make_float2(acc[mi][ni][2] + b0, acc[mi][ni][3] + b1);
            *(float2*)p0 = v0;
            *(float2*)p1 = v1;
        }
    }
}

// ---------------------------------------------------------------------------
// Windowed causal flash attention (SIMT, LDS-optimized).
// Grid: (SEQ/32, NHEAD, BATCH). 256 threads; warp owns 4 query rows.
// ---------------------------------------------------------------------------
#define BQ 32

__global__ __launch_bounds__(256) void attn_kernel(const float* __restrict__ Q,
                                                   const float* __restrict__ K,
                                                   const float* __restrict__ V,
                                                   float* __restrict__ O) {
    __shared__ float Qs[BQ][HDIM];
    __shared__ float Ks[BQ][HDIM + 4];
    __shared__ float Vs[BQ][HDIM + 4];
    __shared__ float Ps[BQ][BQ + 4];

    int qb = blockIdx.x * BQ;
    int h = blockIdx.y;
    int b = blockIdx.z;
    int tid = threadIdx.x;
    int warp = tid >> 5;
    int lane = tid & 31;

    const size_t headbase = ((size_t)b * SEQ) * DIM + (size_t)h * HDIM;
    const float* Qb = Q + headbase + (size_t)qb * DIM;

    for (int i = tid; i < BQ * (HDIM / 4); i += 256) {
        int q = i >> 4;
        int d4 = (i & 15) << 2;
        *(float4*)&Qs[q][d4] = *(const float4*)(Qb + (size_t)q * DIM + d4);
    }

    int kstart = qb - (WIN - 1);
    if (kstart < 0) kstart = 0;
    kstart &= ~31;

    float m[4], l[4], acc0[4], acc1[4];
#pragma unroll
    for (int i = 0; i < 4; i++) {
        m[i] = -1e30f;
        l[i] = 0.0f;
        acc0[i] = 0.0f;
        acc1[i] = 0.0f;
    }

    for (int kt = kstart; kt <= qb; kt += BQ) {
        __syncthreads();

        const float* Kb = K + headbase + (size_t)kt * DIM;
        const float* Vb = V + headbase + (size_t)kt * DIM;
        for (int i = tid; i < BQ * (HDIM / 4); i += 256) {
            int r = i >> 4;
            int d4 = (i & 15) << 2;
            *(float4*)&Ks[r][d4] = *(const float4*)(Kb + (size_t)r * DIM + d4);
            *(float4*)&Vs[r][d4] = *(const float4*)(Vb + (size_t)r * DIM + d4);
        }
        __syncthreads();

        float sc[4] = {0.0f, 0.0f, 0.0f, 0.0f};
#pragma unroll
        for (int d4 = 0; d4 < HDIM; d4 += 4) {
            float4 kv = *(const float4*)&Ks[lane][d4];
#pragma unroll
            for (int qq = 0; qq < 4; qq++) {
                float4 qv = *(const float4*)&Qs[warp * 4 + qq][d4];
                sc[qq] += qv.x * kv.x + qv.y * kv.y + qv.z * kv.z + qv.w * kv.w;
            }
        }

#pragma unroll
        for (int qq = 0; qq < 4; qq++) {
            int q = warp * 4 + qq;
            int qi = qb + q;
            int j = kt + lane;
            bool valid = (j <= qi) && (qi - j < WIN);
            float s = valid ? sc[qq] : -1e30f;
            float tm = s;
#pragma unroll
            for (int off = 16; off; off >>= 1)
                tm = fmaxf(tm, __shfl_xor_sync(0xffffffffu, tm, off));
            float mnew = fmaxf(m[qq], tm);
            float p = valid ? __expf(s - mnew) : 0.0f;
            Ps[q][lane] = p;
            float ps = p;
#pragma unroll
            for (int off = 16; off; off >>= 1)
                ps += __shfl_xor_sync(0xffffffffu, ps, off);
            float corr = __expf(m[qq] - mnew);
            l[qq] = l[qq] * corr + ps;
            m[qq] = mnew;
            acc0[qq] *= corr;
            acc1[qq] *= corr;
        }
        __syncwarp();

#pragma unroll
        for (int k2 = 0; k2 < BQ; k2 += 4) {
            float va0 = Vs[k2 + 0][lane];
            float va1 = Vs[k2 + 1][lane];
            float va2 = Vs[k2 + 2][lane];
            float va3 = Vs[k2 + 3][lane];
            float vb0 = Vs[k2 + 0][lane + 32];
            float vb1 = Vs[k2 + 1][lane + 32];
            float vb2 = Vs[k2 + 2][lane + 32];
            float vb3 = Vs[k2 + 3][lane + 32];
#pragma unroll
            for (int qq = 0; qq < 4; qq++) {
                float4 p = *(const float4*)&Ps[warp * 4 + qq][k2];
                acc0[qq] += p.x * va0 + p.y * va1 + p.z * va2 + p.w * va3;
                acc1[qq] += p.x * vb0 + p.y * vb1 + p.z * vb2 + p.w * vb3;
            }
        }
    }

    float* Ob = O + headbase + (size_t)qb * DIM;
#pragma unroll
    for (int qq = 0; qq < 4; qq++) {
        int q = warp * 4 + qq;
        float inv = 1.0f / l[qq];
        Ob[(size_t)q * DIM + lane] = acc0[qq] * inv;
        Ob[(size_t)q * DIM + lane + 32] = acc1[qq] * inv;
    }
}

// ---------------------------------------------------------------------------
extern "C" void kernel_launch(void* const* d_in, const int* in_sizes, int n_in,
                              void* d_out, int out_size) {
    (void)in_sizes; (void)n_in; (void)out_size;
    const float* X  = (const float*)d_in[0];
    const float* Wq = (const float*)d_in[1];
    const float* Wk = (const float*)d_in[2];
    const float* Wv = (const float*)d_in[3];
    const float* Wo = (const float*)d_in[4];
    const float* bo = (const float*)d_in[5];
    float* out = (float*)d_out;

    float *q, *k, *v, *ctx;
    __nv_bfloat16 *xh, *xl, *ch, *cl;
    __nv_bfloat16 *wqh, *wql, *wkh, *wkl, *wvh, *wvl, *woh, *wol;
    cudaGetSymbolAddress((void**)&q, g_q);
    cudaGetSymbolAddress((void**)&k, g_k);
    cudaGetSymbolAddress((void**)&v, g_v);
    cudaGetSymbolAddress((void**)&ctx, g_ctx);
    cudaGetSymbolAddress((void**)&xh, g_xh);
    cudaGetSymbolAddress((void**)&xl, g_xl);
    cudaGetSymbolAddress((void**)&ch, g_ch);
    cudaGetSymbolAddress((void**)&cl, g_cl);
    cudaGetSymbolAddress((void**)&wqh, g_wqh);
    cudaGetSymbolAddress((void**)&wql, g_wql);
    cudaGetSymbolAddress((void**)&wkh, g_wkh);
    cudaGetSymbolAddress((void**)&wkl, g_wkl);
    cudaGetSymbolAddress((void**)&wvh, g_wvh);
    cudaGetSymbolAddress((void**)&wvl, g_wvl);
    cudaGetSymbolAddress((void**)&woh, g_woh);
    cudaGetSymbolAddress((void**)&wol, g_wol);

    const int DYN = 2 * STAGEB;  // 81920
    cudaFuncSetAttribute(gemm_mma<false>, cudaFuncAttributeMaxDynamicSharedMemorySize, DYN);
    cudaFuncSetAttribute(gemm_mma<true>,  cudaFuncAttributeMaxDynamicSharedMemorySize, DYN);

    const int nX = MROWS * DIM;
    const int nW = DIM * DIM;

    split_bf16<<<nX / 1024, 256>>>(X, xh, xl, nX);
    split_bf16<<<nW / 1024, 256>>>(Wq, wqh, wql, nW);
    split_bf16<<<nW / 1024, 256>>>(Wk, wkh, wkl, nW);
    split_bf16<<<nW / 1024, 256>>>(Wv, wvh, wvl, nW);
    split_bf16<<<nW / 1024, 256>>>(Wo, woh, wol, nW);

    dim3 ggrid(DIM / 128, MROWS / 128);  // (8, 64)
    gemm_mma<false><<<ggrid, 256, DYN>>>(xh, xl, wqh, wql, nullptr, q);
    gemm_mma<false><<<ggrid, 256, DYN>>>(xh, xl, wkh, wkl, nullptr, k);
    gemm_mma<false><<<ggrid, 256, DYN>>>(xh, xl, wvh, wvl, nullptr, v);

    dim3 attn_grid(SEQ / BQ, NHEAD, BATCH);
    attn_kernel<<<attn_grid, 256>>>(q, k, v, ctx);

    split_bf16<<<nX / 1024, 256>>>(ctx, ch, cl, nX);
    gemm_mma<true><<<ggrid, 256, DYN>>>(ch, cl, woh, wol, bo, out);
}

// round 4
// speedup vs baseline: 3.1952x; 1.3228x over previous
#include <cuda_runtime.h>
#include <cuda_bf16.h>
#include <stdint.h>

// Problem constants
#define BATCH 4
#define SEQ   2048
#define DIM   1024
#define NHEAD 16
#define HDIM  64
#define WIN   256
#define MROWS (BATCH * SEQ)   // 8192

// ---------------------------------------------------------------------------
// Scratch (device globals: allocation-free rule)
// ---------------------------------------------------------------------------
__device__ float g_q[MROWS * DIM];
__device__ float g_k[MROWS * DIM];
__device__ float g_v[MROWS * DIM];
__device__ __nv_bfloat16 g_xh[MROWS * DIM];
__device__ __nv_bfloat16 g_xl[MROWS * DIM];
__device__ __nv_bfloat16 g_ch[MROWS * DIM];
__device__ __nv_bfloat16 g_cl[MROWS * DIM];
__device__ __nv_bfloat16 g_wqh[DIM * DIM];
__device__ __nv_bfloat16 g_wql[DIM * DIM];
__device__ __nv_bfloat16 g_wkh[DIM * DIM];
__device__ __nv_bfloat16 g_wkl[DIM * DIM];
__device__ __nv_bfloat16 g_wvh[DIM * DIM];
__device__ __nv_bfloat16 g_wvl[DIM * DIM];
__device__ __nv_bfloat16 g_woh[DIM * DIM];
__device__ __nv_bfloat16 g_wol[DIM * DIM];

// ---------------------------------------------------------------------------
// Portable PTX helpers
// ---------------------------------------------------------------------------
__device__ __forceinline__ uint32_t smem_u32(const void* p) {
    uint32_t a;
    asm("{ .reg .u64 t; cvta.to.shared.u64 t, %1; cvt.u32.u64 %0, t; }"
        : "=r"(a) : "l"(p));
    return a;
}

#define CP_ASYNC16(dst, src) \
    asm volatile("cp.async.cg.shared.global [%0], [%1], 16;" :: "r"(dst), "l"(src))
#define CP_COMMIT() asm volatile("cp.async.commit_group;" ::: "memory")
#define CP_WAIT(n)  asm volatile("cp.async.wait_group %0;" :: "n"(n) : "memory")

__device__ __forceinline__ void ldsm_x4(uint32_t& r0, uint32_t& r1,
                                        uint32_t& r2, uint32_t& r3, uint32_t addr) {
    asm volatile("ldmatrix.sync.aligned.m8n8.x4.shared.b16 {%0,%1,%2,%3}, [%4];"
                 : "=r"(r0), "=r"(r1), "=r"(r2), "=r"(r3) : "r"(addr));
}

__device__ __forceinline__ void mma_bf16(float& c0, float& c1, float& c2, float& c3,
                                         uint32_t a0, uint32_t a1, uint32_t a2, uint32_t a3,
                                         uint32_t b0, uint32_t b1) {
    asm volatile(
        "mma.sync.aligned.m16n8k16.row.col.f32.bf16.bf16.f32 "
        "{%0,%1,%2,%3}, {%4,%5,%6,%7}, {%8,%9}, {%0,%1,%2,%3};"
        : "+f"(c0), "+f"(c1), "+f"(c2), "+f"(c3)
        : "r"(a0), "r"(a1), "r"(a2), "r"(a3), "r"(b0), "r"(b1));
}

__device__ __forceinline__ uint32_t pack_bf2(__nv_bfloat16 a, __nv_bfloat16 b) {
    __nv_bfloat162 t(a, b);
    return *(uint32_t*)&t;
}

// split two floats into packed hi / packed lo bf16x2
__device__ __forceinline__ void split2(float a, float b, uint32_t& hi, uint32_t& lo) {
    __nv_bfloat16 ha = __float2bfloat16(a), hb = __float2bfloat16(b);
    float ra = a - __bfloat162float(ha);
    float rb = b - __bfloat162float(hb);
    hi = pack_bf2(ha, hb);
    lo = pack_bf2(__float2bfloat16(ra), __float2bfloat16(rb));
}

// ---------------------------------------------------------------------------
// fp32 -> bf16 hi/lo split
// ---------------------------------------------------------------------------
__global__ __launch_bounds__(256) void split_bf16(const float* __restrict__ src,
                                                  __nv_bfloat16* __restrict__ hi,
                                                  __nv_bfloat16* __restrict__ lo,
                                                  int n) {
    int i = (blockIdx.x * 256 + threadIdx.x) * 4;
    if (i >= n) return;
    float4 x = *(const float4*)(src + i);
    uint32_t h0, l0, h1, l1;
    split2(x.x, x.y, h0, l0);
    split2(x.z, x.w, h1, l1);
    uint32_t* ph = (uint32_t*)(hi + i);
    uint32_t* pl = (uint32_t*)(lo + i);
    ph[0] = h0; ph[1] = h1;
    pl[0] = l0; pl[1] = l1;
}

// ---------------------------------------------------------------------------
// HMMA bf16-split GEMM core (verified in R3)
// ---------------------------------------------------------------------------
#define GP      40
#define TBYTES  (128 * GP * 2)
#define STAGEB  (4 * TBYTES)
#define NCH     (DIM / 32)

template <bool HAS_BIAS>
__device__ __forceinline__ void gemm_body(const __nv_bfloat16* Ah, const __nv_bfloat16* Al,
                                          const __nv_bfloat16* Bh, const __nv_bfloat16* Bl,
                                          const float* bias, float* C,
                                          int bm, int bn, char* smem) {
    const int tid = threadIdx.x;
    const int wid = tid >> 5;
    const int lane = tid & 31;
    const int wm = (wid & 1) * 64;
    const int wn = (wid >> 1) * 32;
    const uint32_t sbase = smem_u32(smem);

    const char* gAh = (const char*)Ah + (size_t)bm * (DIM * 2);
    const char* gAl = (const char*)Al + (size_t)bm * (DIM * 2);
    const char* gBh = (const char*)Bh + (size_t)bn * (DIM * 2);
    const char* gBl = (const char*)Bl + (size_t)bn * (DIM * 2);

    auto issue = [&](int c, int s) {
        char* st = smem + s * STAGEB;
        const size_t gk = (size_t)c * 64;
#pragma unroll
        for (int rep = 0; rep < 2; rep++) {
            int t = rep ? (tid + 256) : tid;
            int r = t >> 2;
            int cc = (t & 3) << 4;
            uint32_t dst = smem_u32(st) + r * 80 + cc;
            size_t src = (size_t)r * (DIM * 2) + gk + cc;
            CP_ASYNC16(dst,              gAh + src);
            CP_ASYNC16(dst + TBYTES,     gAl + src);
            CP_ASYNC16(dst + 2 * TBYTES, gBh + src);
            CP_ASYNC16(dst + 3 * TBYTES, gBl + src);
        }
    };

    float acc[4][4][4];
#pragma unroll
    for (int i = 0; i < 4; i++)
#pragma unroll
        for (int j = 0; j < 4; j++)
#pragma unroll
            for (int r = 0; r < 4; r++) acc[i][j][r] = 0.0f;

    const int a_r = lane & 15, a_c = (lane >> 4) * 8;
    const int b_r = (lane & 7) + ((lane >> 4) & 1) * 8, b_c = ((lane >> 3) & 1) * 8;

    issue(0, 0);
    CP_COMMIT();

    for (int c = 0; c < NCH; ++c) {
        const int s = c & 1;
        if (c + 1 < NCH) {
            issue(c + 1, s ^ 1);
            CP_COMMIT();
            CP_WAIT(1);
        } else {
            CP_WAIT(0);
        }
        __syncthreads();

        const uint32_t st = sbase + s * STAGEB;
        const uint32_t pAh = st;
        const uint32_t pAl = st + TBYTES;
        const uint32_t pBh = st + 2 * TBYTES;
        const uint32_t pBl = st + 3 * TBYTES;

#pragma unroll
        for (int kk = 0; kk < 32; kk += 16) {
            uint32_t ah[4][4], al[4][4];
#pragma unroll
            for (int mi = 0; mi < 4; mi++) {
                uint32_t off = (uint32_t)((wm + mi * 16 + a_r) * 80 + (kk + a_c) * 2);
                ldsm_x4(ah[mi][0], ah[mi][1], ah[mi][2], ah[mi][3], pAh + off);
                ldsm_x4(al[mi][0], al[mi][1], al[mi][2], al[mi][3], pAl + off);
            }
            uint32_t bh[4][2], bl[4][2];
#pragma unroll
            for (int nb = 0; nb < 2; nb++) {
                uint32_t off = (uint32_t)((wn + nb * 16 + b_r) * 80 + (kk + b_c) * 2);
                uint32_t r0, r1, r2, r3;
                ldsm_x4(r0, r1, r2, r3, pBh + off);
                bh[nb * 2][0] = r0; bh[nb * 2][1] = r1;
                bh[nb * 2 + 1][0] = r2; bh[nb * 2 + 1][1] = r3;
                ldsm_x4(r0, r1, r2, r3, pBl + off);
                bl[nb * 2][0] = r0; bl[nb * 2][1] = r1;
                bl[nb * 2 + 1][0] = r2; bl[nb * 2 + 1][1] = r3;
            }
#pragma unroll
            for (int mi = 0; mi < 4; mi++)
#pragma unroll
                for (int ni = 0; ni < 4; ni++) {
                    mma_bf16(acc[mi][ni][0], acc[mi][ni][1], acc[mi][ni][2], acc[mi][ni][3],
                             ah[mi][0], ah[mi][1], ah[mi][2], ah[mi][3],
                             bh[ni][0], bh[ni][1]);
                    mma_bf16(acc[mi][ni][0], acc[mi][ni][1], acc[mi][ni][2], acc[mi][ni][3],
                             ah[mi][0], ah[mi][1], ah[mi][2], ah[mi][3],
                             bl[ni][0], bl[ni][1]);
                    mma_bf16(acc[mi][ni][0], acc[mi][ni][1], acc[mi][ni][2], acc[mi][ni][3],
                             al[mi][0], al[mi][1], al[mi][2], al[mi][3],
                             bh[ni][0], bh[ni][1]);
                }
        }
        __syncthreads();
    }

    const int er = lane >> 2;
    const int ec = (lane & 3) * 2;
#pragma unroll
    for (int mi = 0; mi < 4; mi++) {
#pragma unroll
        for (int ni = 0; ni < 4; ni++) {
            int col = bn + wn + ni * 8 + ec;
            float b0 = 0.f, b1 = 0.f;
            if (HAS_BIAS) { b0 = bias[col]; b1 = bias[col + 1]; }
            float* p0 = C + (size_t)(bm + wm + mi * 16 + er) * DIM + col;
            float* p1 = C + (size_t)(bm + wm + mi * 16 + er + 8) * DIM + col;
            *(float2*)p0 = make_float2(acc[mi][ni][0] + b0, acc[mi][ni][1] + b1);
            *(float2*)p1 = make_float2(acc[mi][ni][2] + b0, acc[mi][ni][3] + b1);
        }
    }
}

// Fused Q/K/V projection: blockIdx.z selects weight/output
__global__ __launch_bounds__(256) void gemm_qkv(const __nv_bfloat16* __restrict__ xh,
                                                const __nv_bfloat16* __restrict__ xl,
                                                const __nv_bfloat16* __restrict__ wqh,
                                                const __nv_bfloat16* __restrict__ wql,
                                                const __nv_bfloat16* __restrict__ wkh,
                                                const __nv_bfloat16* __restrict__ wkl,
                                                const __nv_bfloat16* __restrict__ wvh,
                                                const __nv_bfloat16* __restrict__ wvl,
                                                float* __restrict__ q,
                                                float* __restrict__ k,
                                                float* __restrict__ v) {
    extern __shared__ char smem[];
    const __nv_bfloat16* bh = (blockIdx.z == 0) ? wqh : (blockIdx.z == 1) ? wkh : wvh;
    const __nv_bfloat16* bl = (blockIdx.z == 0) ? wql : (blockIdx.z == 1) ? wkl : wvl;
    float* out = (blockIdx.z == 0) ? q : (blockIdx.z == 1) ? k : v;
    gemm_body<false>(xh, xl, bh, bl, nullptr, out, blockIdx.y * 128, blockIdx.x * 128, smem);
}

__global__ __launch_bounds__(256) void gemm_out(const __nv_bfloat16* __restrict__ ah,
                                                const __nv_bfloat16* __restrict__ al,
                                                const __nv_bfloat16* __restrict__ bh,
                                                const __nv_bfloat16* __restrict__ bl,
                                                const float* __restrict__ bias,
                                                float* __restrict__ C) {
    extern __shared__ char smem[];
    gemm_body<true>(ah, al, bh, bl, bias, C, blockIdx.y * 128, blockIdx.x * 128, smem);
}

// ---------------------------------------------------------------------------
// HMMA windowed flash attention.
// Block: 128 threads (4 warps), 64 queries, one (b,h). Warp owns 16 q rows.
// Key tiles of 64. Q/K in smem [row][d] pitch 72; V transposed [d][key].
// Writes ctx directly as bf16 hi/lo.
// ---------------------------------------------------------------------------
#define AP 72                       // smem pitch (bf16 elems) = 144B
#define ATILE (64 * AP * 2)         // 9216 bytes per tile
#define ADYN  (6 * ATILE)           // Qh Ql Kh Kl Vh Vl = 55296

__global__ __launch_bounds__(128) void attn_mma(const float* __restrict__ Q,
                                                const float* __restrict__ K,
                                                const float* __restrict__ V,
                                                __nv_bfloat16* __restrict__ ch,
                                                __nv_bfloat16* __restrict__ cl) {
    extern __shared__ char smem[];
    const uint32_t sQh = smem_u32(smem);
    const uint32_t sQl = sQh + ATILE;
    const uint32_t sKh = sQh + 2 * ATILE;
    const uint32_t sKl = sQh + 3 * ATILE;
    const uint32_t sVh = sQh + 4 * ATILE;   // transposed: [d][key]
    const uint32_t sVl = sQh + 5 * ATILE;

    const int qb = blockIdx.x * 64;
    const int h = blockIdx.y;
    const int b = blockIdx.z;
    const int tid = threadIdx.x;
    const int warp = tid >> 5;
    const int lane = tid & 31;

    const size_t headbase = ((size_t)b * SEQ) * DIM + (size_t)h * HDIM;

    // ---- load Q tile (64x64 fp32 -> bf16 hi/lo) ----
    {
        const float* Qb = Q + headbase + (size_t)qb * DIM;
        for (int i = tid; i < 64 * 16; i += 128) {
            int r = i >> 4;
            int d4 = (i & 15) << 2;
            float4 x = *(const float4*)(Qb + (size_t)r * DIM + d4);
            uint32_t h0, l0, h1, l1;
            split2(x.x, x.y, h0, l0);
            split2(x.z, x.w, h1, l1);
            uint32_t off = (uint32_t)(r * AP + d4) * 2;
            *(uint32_t*)(smem + (sQh - smem_u32(smem)) + off) = h0;  // avoid generic: use direct
            // (use byte pointers relative to smem base)
            ((uint32_t*)(smem + 0 * ATILE + off))[0] = h0;
            ((uint32_t*)(smem + 0 * ATILE + off))[1] = h1;
            ((uint32_t*)(smem + 1 * ATILE + off))[0] = l0;
            ((uint32_t*)(smem + 1 * ATILE + off))[1] = l1;
        }
    }
    __syncthreads();

    // ---- preload Q A-frags: 4 d-slices x (hi,lo) ----
    const int a_r = lane & 15, a_c = (lane >> 4) * 8;
    const int b_r = (lane & 7) + ((lane >> 4) & 1) * 8, b_c = ((lane >> 3) & 1) * 8;

    uint32_t qh[4][4], ql[4][4];
#pragma unroll
    for (int t = 0; t < 4; t++) {
        uint32_t off = (uint32_t)((warp * 16 + a_r) * AP + t * 16 + a_c) * 2;
        ldsm_x4(qh[t][0], qh[t][1], qh[t][2], qh[t][3], sQh + off);
        ldsm_x4(ql[t][0], ql[t][1], ql[t][2], ql[t][3], sQl + off);
    }

    // online softmax state: 2 rows per thread (r, r+8)
    float m0 = -1e30f, m1 = -1e30f, l0 = 0.0f, l1 = 0.0f;
    float o[8][4];
#pragma unroll
    for (int j = 0; j < 8; j++)
#pragma unroll
        for (int r = 0; r < 4; r++) o[j][r] = 0.0f;

    int kstart = qb - (WIN - 1);
    if (kstart < 0) kstart = 0;
    kstart &= ~63;
    const int kend = qb + 63;

    const int row0 = qb + warp * 16 + (lane >> 2);
    const int row1 = row0 + 8;

    for (int kt = kstart; kt <= kend; kt += 64) {
        __syncthreads();
        // ---- load K (row-major) and V (transposed) tiles ----
        {
            const float* Kb = K + headbase + (size_t)kt * DIM;
            const float* Vb = V + headbase + (size_t)kt * DIM;
            for (int i = tid; i < 64 * 16; i += 128) {
                int r = i >> 4;
                int d4 = (i & 15) << 2;
                float4 x = *(const float4*)(Kb + (size_t)r * DIM + d4);
                uint32_t h0, lo0, h1, lo1;
                split2(x.x, x.y, h0, lo0);
                split2(x.z, x.w, h1, lo1);
                uint32_t off = (uint32_t)(r * AP + d4) * 2;
                ((uint32_t*)(smem + 2 * ATILE + off))[0] = h0;
                ((uint32_t*)(smem + 2 * ATILE + off))[1] = h1;
                ((uint32_t*)(smem + 3 * ATILE + off))[0] = lo0;
                ((uint32_t*)(smem + 3 * ATILE + off))[1] = lo1;

                float4 y = *(const float4*)(Vb + (size_t)r * DIM + d4);
                // transpose: Vt[d][key=r]
                __nv_bfloat16 vh[4], vl[4];
                float vv[4] = {y.x, y.y, y.z, y.w};
#pragma unroll
                for (int j = 0; j < 4; j++) {
                    vh[j] = __float2bfloat16(vv[j]);
                    vl[j] = __float2bfloat16(vv[j] - __bfloat162float(vh[j]));
                }
#pragma unroll
                for (int j = 0; j < 4; j++) {
                    uint32_t toff = (uint32_t)((d4 + j) * AP + r) * 2;
                    *(__nv_bfloat16*)(smem + 4 * ATILE + toff) = vh[j];
                    *(__nv_bfloat16*)(smem + 5 * ATILE + toff) = vl[j];
                }
            }
        }
        __syncthreads();

        // ---- scores S = Q K^T (3-pass) ----
        float acc[8][4];
#pragma unroll
        for (int j = 0; j < 8; j++)
#pragma unroll
            for (int r = 0; r < 4; r++) acc[j][r] = 0.0f;

#pragma unroll
        for (int t = 0; t < 4; t++) {
#pragma unroll
            for (int g = 0; g < 4; g++) {
                uint32_t off = (uint32_t)((g * 16 + b_r) * AP + t * 16 + b_c) * 2;
                uint32_t kh0, kh1, kh2, kh3, kl0, kl1, kl2, kl3;
                ldsm_x4(kh0, kh1, kh2, kh3, sKh + off);
                ldsm_x4(kl0, kl1, kl2, kl3, sKl + off);
                int n0 = 2 * g, n1 = 2 * g + 1;
                mma_bf16(acc[n0][0], acc[n0][1], acc[n0][2], acc[n0][3],
                         qh[t][0], qh[t][1], qh[t][2], qh[t][3], kh0, kh1);
                mma_bf16(acc[n0][0], acc[n0][1], acc[n0][2], acc[n0][3],
                         qh[t][0], qh[t][1], qh[t][2], qh[t][3], kl0, kl1);
                mma_bf16(acc[n0][0], acc[n0][1], acc[n0][2], acc[n0][3],
                         ql[t][0], ql[t][1], ql[t][2], ql[t][3], kh0, kh1);
                mma_bf16(acc[n1][0], acc[n1][1], acc[n1][2], acc[n1][3],
                         qh[t][0], qh[t][1], qh[t][2], qh[t][3], kh2, kh3);
                mma_bf16(acc[n1][0], acc[n1][1], acc[n1][2], acc[n1][3],
                         qh[t][0], qh[t][1], qh[t][2], qh[t][3], kl2, kl3);
                mma_bf16(acc[n1][0], acc[n1][1], acc[n1][2], acc[n1][3],
                         ql[t][0], ql[t][1], ql[t][2], ql[t][3], kh2, kh3);
            }
        }

        // ---- mask + online softmax ----
        float tmax0 = -1e30f, tmax1 = -1e30f;
#pragma unroll
        for (int j = 0; j < 8; j++) {
            int colb = kt + 8 * j + 2 * (lane & 3);
#pragma unroll
            for (int e = 0; e < 2; e++) {
                int col = colb + e;
                bool v0 = (col <= row0) && (row0 - col < WIN);
                bool v1 = (col <= row1) && (row1 - col < WIN);
                if (!v0) acc[j][e] = -1e30f;
                if (!v1) acc[j][2 + e] = -1e30f;
            }
            tmax0 = fmaxf(tmax0, fmaxf(acc[j][0], acc[j][1]));
            tmax1 = fmaxf(tmax1, fmaxf(acc[j][2], acc[j][3]));
        }
#pragma unroll
        for (int off = 1; off <= 2; off <<= 1) {
            tmax0 = fmaxf(tmax0, __shfl_xor_sync(0xffffffffu, tmax0, off));
            tmax1 = fmaxf(tmax1, __shfl_xor_sync(0xffffffffu, tmax1, off));
        }
        float mn0 = fmaxf(m0, tmax0);
        float mn1 = fmaxf(m1, tmax1);

        float rs0 = 0.0f, rs1 = 0.0f;
#pragma unroll
        for (int j = 0; j < 8; j++) {
            acc[j][0] = __expf(acc[j][0] - mn0);
            acc[j][1] = __expf(acc[j][1] - mn0);
            acc[j][2] = __expf(acc[j][2] - mn1);
            acc[j][3] = __expf(acc[j][3] - mn1);
            rs0 += acc[j][0] + acc[j][1];
            rs1 += acc[j][2] + acc[j][3];
        }
#pragma unroll
        for (int off = 1; off <= 2; off <<= 1) {
            rs0 += __shfl_xor_sync(0xffffffffu, rs0, off);
            rs1 += __shfl_xor_sync(0xffffffffu, rs1, off);
        }
        float corr0 = __expf(m0 - mn0);
        float corr1 = __expf(m1 - mn1);
        l0 = l0 * corr0 + rs0;
        l1 = l1 * corr1 + rs1;
        m0 = mn0;
        m1 = mn1;
#pragma unroll
        for (int j = 0; j < 8; j++) {
            o[j][0] *= corr0;
            o[j][1] *= corr0;
            o[j][2] *= corr1;
            o[j][3] *= corr1;
        }

        // ---- O += P V (3-pass, P from registers) ----
#pragma unroll
        for (int t = 0; t < 4; t++) {   // key 16-slices
            uint32_t ah[4], al[4];
            split2(acc[2 * t][0], acc[2 * t][1], ah[0], al[0]);
            split2(acc[2 * t][2], acc[2 * t][3], ah[1], al[1]);
            split2(acc[2 * t + 1][0], acc[2 * t + 1][1], ah[2], al[2]);
            split2(acc[2 * t + 1][2], acc[2 * t + 1][3], ah[3], al[3]);
#pragma unroll
            for (int g = 0; g < 4; g++) {  // d 16-groups
                uint32_t off = (uint32_t)((g * 16 + b_r) * AP + t * 16 + b_c) * 2;
                uint32_t vh0, vh1, vh2, vh3, vl0, vl1, vl2, vl3;
                ldsm_x4(vh0, vh1, vh2, vh3, sVh + off);
                ldsm_x4(vl0, vl1, vl2, vl3, sVl + off);
                int n0 = 2 * g, n1 = 2 * g + 1;
                mma_bf16(o[n0][0], o[n0][1], o[n0][2], o[n0][3],
                         ah[0], ah[1], ah[2], ah[3], vh0, vh1);
                mma_bf16(o[n0][0], o[n0][1], o[n0][2], o[n0][3],
                         ah[0], ah[1], ah[2], ah[3], vl0, vl1);
                mma_bf16(o[n0][0], o[n0][1], o[n0][2], o[n0][3],
                         al[0], al[1], al[2], al[3], vh0, vh1);
                mma_bf16(o[n1][0], o[n1][1], o[n1][2], o[n1][3],
                         ah[0], ah[1], ah[2], ah[3], vh2, vh3);
                mma_bf16(o[n1][0], o[n1][1], o[n1][2], o[n1][3],
                         ah[0], ah[1], ah[2], ah[3], vl2, vl3);
                mma_bf16(o[n1][0], o[n1][1], o[n1][2], o[n1][3],
                         al[0], al[1], al[2], al[3], vh2, vh3);
            }
        }
    }

    // ---- epilogue: normalize, split to bf16 hi/lo ctx ----
    float inv0 = 1.0f / l0;
    float inv1 = 1.0f / l1;
    const size_t tok0 = (size_t)b * SEQ + row0;
    const size_t tok1 = (size_t)b * SEQ + row1;
    const int colbase = h * HDIM + 2 * (lane & 3);
#pragma unroll
    for (int j = 0; j < 8; j++) {
        int col = colbase + 8 * j;
        uint32_t h0, lo0, h1, lo1;
        split2(o[j][0] * inv0, o[j][1] * inv0, h0, lo0);
        split2(o[j][2] * inv1, o[j][3] * inv1, h1, lo1);
        *(uint32_t*)(ch + tok0 * DIM + col) = h0;
        *(uint32_t*)(cl + tok0 * DIM + col) = lo0;
        *(uint32_t*)(ch + tok1 * DIM + col) = h1;
        *(uint32_t*)(cl + tok1 * DIM + col) = lo1;
    }
}

// ---------------------------------------------------------------------------
extern "C" void kernel_launch(void* const* d_in, const int* in_sizes, int n_in,
                              void* d_out, int out_size) {
    (void)in_sizes; (void)n_in; (void)out_size;
    const float* X  = (const float*)d_in[0];
    const float* Wq = (const float*)d_in[1];
    const float* Wk = (const float*)d_in[2];
    const float* Wv = (const float*)d_in[3];
    const float* Wo = (const float*)d_in[4];
    const float* bo = (const float*)d_in[5];
    float* out = (float*)d_out;

    float *q, *k, *v;
    __nv_bfloat16 *xh, *xl, *ch, *cl;
    __nv_bfloat16 *wqh, *wql, *wkh, *wkl, *wvh, *wvl, *woh, *wol;
    cudaGetSymbolAddress((void**)&q, g_q);
    cudaGetSymbolAddress((void**)&k, g_k);
    cudaGetSymbolAddress((void**)&v, g_v);
    cudaGetSymbolAddress((void**)&xh, g_xh);
    cudaGetSymbolAddress((void**)&xl, g_xl);
    cudaGetSymbolAddress((void**)&ch, g_ch);
    cudaGetSymbolAddress((void**)&cl, g_cl);
    cudaGetSymbolAddress((void**)&wqh, g_wqh);
    cudaGetSymbolAddress((void**)&wql, g_wql);
    cudaGetSymbolAddress((void**)&wkh, g_wkh);
    cudaGetSymbolAddress((void**)&wkl, g_wkl);
    cudaGetSymbolAddress((void**)&wvh, g_wvh);
    cudaGetSymbolAddress((void**)&wvl, g_wvl);
    cudaGetSymbolAddress((void**)&woh, g_woh);
    cudaGetSymbolAddress((void**)&wol, g_wol);

    const int DYN = 2 * STAGEB;
    cudaFuncSetAttribute(gemm_qkv, cudaFuncAttributeMaxDynamicSharedMemorySize, DYN);
    cudaFuncSetAttribute(gemm_out, cudaFuncAttributeMaxDynamicSharedMemorySize, DYN);
    cudaFuncSetAttribute(attn_mma, cudaFuncAttributeMaxDynamicSharedMemorySize, ADYN);

    const int nX = MROWS * DIM;
    const int nW = DIM * DIM;

    split_bf16<<<nX / 1024, 256>>>(X, xh, xl, nX);
    split_bf16<<<nW / 1024, 256>>>(Wq, wqh, wql, nW);
    split_bf16<<<nW / 1024, 256>>>(Wk, wkh, wkl, nW);
    split_bf16<<<nW / 1024, 256>>>(Wv, wvh, wvl, nW);
    split_bf16<<<nW / 1024, 256>>>(Wo, woh, wol, nW);

    dim3 qkv_grid(DIM / 128, MROWS / 128, 3);
    gemm_qkv<<<qkv_grid, 256, DYN>>>(xh, xl, wqh, wql, wkh, wkl, wvh, wvl, q, k, v);

    dim3 attn_grid(SEQ / 64, NHEAD, BATCH);
    attn_mma<<<attn_grid, 128, ADYN>>>(q, k, v, ch, cl);

    dim3 ogrid(DIM / 128, MROWS / 128);
    gemm_out<<<ogrid, 256, DYN>>>(ch, cl, woh, wol, bo, out);
}

// round 6
// speedup vs baseline: 3.4528x; 1.0806x over previous
#include <cuda_runtime.h>
#include <cuda_bf16.h>
#include <stdint.h>

// Problem constants
#define BATCH 4
#define SEQ   2048
#define DIM   1024
#define NHEAD 16
#define HDIM  64
#define WIN   256
#define MROWS (BATCH * SEQ)   // 8192

// ---------------------------------------------------------------------------
// Scratch (device globals: allocation-free rule)
// ---------------------------------------------------------------------------
__device__ __nv_bfloat16 g_qh[MROWS * DIM];
__device__ __nv_bfloat16 g_ql[MROWS * DIM];
__device__ __nv_bfloat16 g_kh[MROWS * DIM];
__device__ __nv_bfloat16 g_kl[MROWS * DIM];
__device__ __nv_bfloat16 g_vh[MROWS * DIM];
__device__ __nv_bfloat16 g_vl[MROWS * DIM];
__device__ __nv_bfloat16 g_xh[MROWS * DIM];
__device__ __nv_bfloat16 g_xl[MROWS * DIM];
__device__ __nv_bfloat16 g_ch[MROWS * DIM];
__device__ __nv_bfloat16 g_cl[MROWS * DIM];
__device__ __nv_bfloat16 g_wqh[DIM * DIM];
__device__ __nv_bfloat16 g_wql[DIM * DIM];
__device__ __nv_bfloat16 g_wkh[DIM * DIM];
__device__ __nv_bfloat16 g_wkl[DIM * DIM];
__device__ __nv_bfloat16 g_wvh[DIM * DIM];
__device__ __nv_bfloat16 g_wvl[DIM * DIM];
__device__ __nv_bfloat16 g_woh[DIM * DIM];
__device__ __nv_bfloat16 g_wol[DIM * DIM];

// ---------------------------------------------------------------------------
// Portable PTX helpers
// ---------------------------------------------------------------------------
__device__ __forceinline__ uint32_t smem_u32(const void* p) {
    uint32_t a;
    asm("{ .reg .u64 t; cvta.to.shared.u64 t, %1; cvt.u32.u64 %0, t; }"
        : "=r"(a) : "l"(p));
    return a;
}

#define CP_ASYNC16(dst, src) \
    asm volatile("cp.async.cg.shared.global [%0], [%1], 16;" :: "r"(dst), "l"(src))
#define CP_COMMIT() asm volatile("cp.async.commit_group;" ::: "memory")
#define CP_WAIT(n)  asm volatile("cp.async.wait_group %0;" :: "n"(n) : "memory")

__device__ __forceinline__ void ldsm_x4(uint32_t& r0, uint32_t& r1,
                                        uint32_t& r2, uint32_t& r3, uint32_t addr) {
    asm volatile("ldmatrix.sync.aligned.m8n8.x4.shared.b16 {%0,%1,%2,%3}, [%4];"
                 : "=r"(r0), "=r"(r1), "=r"(r2), "=r"(r3) : "r"(addr));
}

__device__ __forceinline__ void ldsm_x4_t(uint32_t& r0, uint32_t& r1,
                                          uint32_t& r2, uint32_t& r3, uint32_t addr) {
    asm volatile("ldmatrix.sync.aligned.m8n8.x4.trans.shared.b16 {%0,%1,%2,%3}, [%4];"
                 : "=r"(r0), "=r"(r1), "=r"(r2), "=r"(r3) : "r"(addr));
}

__device__ __forceinline__ void mma_bf16(float& c0, float& c1, float& c2, float& c3,
                                         uint32_t a0, uint32_t a1, uint32_t a2, uint32_t a3,
                                         uint32_t b0, uint32_t b1) {
    asm volatile(
        "mma.sync.aligned.m16n8k16.row.col.f32.bf16.bf16.f32 "
        "{%0,%1,%2,%3}, {%4,%5,%6,%7}, {%8,%9}, {%0,%1,%2,%3};"
        : "+f"(c0), "+f"(c1), "+f"(c2), "+f"(c3)
        : "r"(a0), "r"(a1), "r"(a2), "r"(a3), "r"(b0), "r"(b1));
}

__device__ __forceinline__ uint32_t pack_bf2(__nv_bfloat16 a, __nv_bfloat16 b) {
    __nv_bfloat162 t(a, b);
    return *(uint32_t*)&t;
}

__device__ __forceinline__ void split2(float a, float b, uint32_t& hi, uint32_t& lo) {
    __nv_bfloat16 ha = __float2bfloat16(a), hb = __float2bfloat16(b);
    float ra = a - __bfloat162float(ha);
    float rb = b - __bfloat162float(hb);
    hi = pack_bf2(ha, hb);
    lo = pack_bf2(__float2bfloat16(ra), __float2bfloat16(rb));
}

// ---------------------------------------------------------------------------
// fp32 -> bf16 hi/lo split
// ---------------------------------------------------------------------------
__global__ __launch_bounds__(256) void split_bf16(const float* __restrict__ src,
                                                  __nv_bfloat16* __restrict__ hi,
                                                  __nv_bfloat16* __restrict__ lo,
                                                  int n) {
    int i = (blockIdx.x * 256 + threadIdx.x) * 4;
    if (i >= n) return;
    float4 x = *(const float4*)(src + i);
    uint32_t h0, l0, h1, l1;
    split2(x.x, x.y, h0, l0);
    split2(x.z, x.w, h1, l1);
    uint32_t* ph = (uint32_t*)(hi + i);
    uint32_t* pl = (uint32_t*)(lo + i);
    ph[0] = h0; ph[1] = h1;
    pl[0] = l0; pl[1] = l1;
}

// ---------------------------------------------------------------------------
// HMMA bf16-split GEMM core (fragment maps verified R3/R4)
// Rows here are 32 bf16 = 64B data, pitch 80B.
// BF16OUT=true: write bf16 hi/lo pair buffers; else fp32 (+bias)
// ---------------------------------------------------------------------------
#define GP      40
#define TBYTES  (128 * GP * 2)
#define STAGEB  (4 * TBYTES)
#define NCH     (DIM / 32)

template <bool BF16OUT>
__device__ __forceinline__ void gemm_body(const __nv_bfloat16* Ah, const __nv_bfloat16* Al,
                                          const __nv_bfloat16* Bh, const __nv_bfloat16* Bl,
                                          const float* bias, float* C,
                                          __nv_bfloat16* Ch, __nv_bfloat16* Cl,
                                          int bm, int bn, char* smem) {
    const int tid = threadIdx.x;
    const int wid = tid >> 5;
    const int lane = tid & 31;
    const int wm = (wid & 1) * 64;
    const int wn = (wid >> 1) * 32;
    const uint32_t sbase = smem_u32(smem);

    const char* gAh = (const char*)Ah + (size_t)bm * (DIM * 2);
    const char* gAl = (const char*)Al + (size_t)bm * (DIM * 2);
    const char* gBh = (const char*)Bh + (size_t)bn * (DIM * 2);
    const char* gBl = (const char*)Bl + (size_t)bn * (DIM * 2);

    auto issue = [&](int c, int s) {
        char* st = smem + s * STAGEB;
        const size_t gk = (size_t)c * 64;
#pragma unroll
        for (int rep = 0; rep < 2; rep++) {
            int t = rep ? (tid + 256) : tid;
            int r = t >> 2;
            int cc = (t & 3) << 4;
            uint32_t dst = smem_u32(st) + r * 80 + cc;
            size_t src = (size_t)r * (DIM * 2) + gk + cc;
            CP_ASYNC16(dst,              gAh + src);
            CP_ASYNC16(dst + TBYTES,     gAl + src);
            CP_ASYNC16(dst + 2 * TBYTES, gBh + src);
            CP_ASYNC16(dst + 3 * TBYTES, gBl + src);
        }
    };

    float acc[4][4][4];
#pragma unroll
    for (int i = 0; i < 4; i++)
#pragma unroll
        for (int j = 0; j < 4; j++)
#pragma unroll
            for (int r = 0; r < 4; r++) acc[i][j][r] = 0.0f;

    const int a_r = lane & 15, a_c = (lane >> 4) * 8;
    const int b_r = (lane & 7) + ((lane >> 4) & 1) * 8, b_c = ((lane >> 3) & 1) * 8;

    issue(0, 0);
    CP_COMMIT();

    for (int c = 0; c < NCH; ++c) {
        const int s = c & 1;
        if (c + 1 < NCH) {
            issue(c + 1, s ^ 1);
            CP_COMMIT();
            CP_WAIT(1);
        } else {
            CP_WAIT(0);
        }
        __syncthreads();

        const uint32_t st = sbase + s * STAGEB;
        const uint32_t pAh = st;
        const uint32_t pAl = st + TBYTES;
        const uint32_t pBh = st + 2 * TBYTES;
        const uint32_t pBl = st + 3 * TBYTES;

#pragma unroll
        for (int kk = 0; kk < 32; kk += 16) {
            uint32_t ah[4][4], al[4][4];
#pragma unroll
            for (int mi = 0; mi < 4; mi++) {
                uint32_t off = (uint32_t)((wm + mi * 16 + a_r) * 80 + (kk + a_c) * 2);
                ldsm_x4(ah[mi][0], ah[mi][1], ah[mi][2], ah[mi][3], pAh + off);
                ldsm_x4(al[mi][0], al[mi][1], al[mi][2], al[mi][3], pAl + off);
            }
            uint32_t bh[4][2], bl[4][2];
#pragma unroll
            for (int nb = 0; nb < 2; nb++) {
                uint32_t off = (uint32_t)((wn + nb * 16 + b_r) * 80 + (kk + b_c) * 2);
                uint32_t r0, r1, r2, r3;
                ldsm_x4(r0, r1, r2, r3, pBh + off);
                bh[nb * 2][0] = r0; bh[nb * 2][1] = r1;
                bh[nb * 2 + 1][0] = r2; bh[nb * 2 + 1][1] = r3;
                ldsm_x4(r0, r1, r2, r3, pBl + off);
                bl[nb * 2][0] = r0; bl[nb * 2][1] = r1;
                bl[nb * 2 + 1][0] = r2; bl[nb * 2 + 1][1] = r3;
            }
#pragma unroll
            for (int mi = 0; mi < 4; mi++)
#pragma unroll
                for (int ni = 0; ni < 4; ni++) {
                    mma_bf16(acc[mi][ni][0], acc[mi][ni][1], acc[mi][ni][2], acc[mi][ni][3],
                             ah[mi][0], ah[mi][1], ah[mi][2], ah[mi][3],
                             bh[ni][0], bh[ni][1]);
                    mma_bf16(acc[mi][ni][0], acc[mi][ni][1], acc[mi][ni][2], acc[mi][ni][3],
                             ah[mi][0], ah[mi][1], ah[mi][2], ah[mi][3],
                             bl[ni][0], bl[ni][1]);
                    mma_bf16(acc[mi][ni][0], acc[mi][ni][1], acc[mi][ni][2], acc[mi][ni][3],
                             al[mi][0], al[mi][1], al[mi][2], al[mi][3],
                             bh[ni][0], bh[ni][1]);
                }
        }
        __syncthreads();
    }

    const int er = lane >> 2;
    const int ec = (lane & 3) * 2;
#pragma unroll
    for (int mi = 0; mi < 4; mi++) {
#pragma unroll
        for (int ni = 0; ni < 4; ni++) {
            int col = bn + wn + ni * 8 + ec;
            int row0 = bm + wm + mi * 16 + er;
            int row1 = row0 + 8;
            if (BF16OUT) {
                uint32_t h0, l0, h1, l1;
                split2(acc[mi][ni][0], acc[mi][ni][1], h0, l0);
                split2(acc[mi][ni][2], acc[mi][ni][3], h1, l1);
                *(uint32_t*)(Ch + (size_t)row0 * DIM + col) = h0;
                *(uint32_t*)(Cl + (size_t)row0 * DIM + col) = l0;
                *(uint32_t*)(Ch + (size_t)row1 * DIM + col) = h1;
                *(uint32_t*)(Cl + (size_t)row1 * DIM + col) = l1;
            } else {
                float b0 = bias[col], b1 = bias[col + 1];
                *(float2*)(C + (size_t)row0 * DIM + col) =
                    make_float2(acc[mi][ni][0] + b0, acc[mi][ni][1] + b1);
                *(float2*)(C + (size_t)row1 * DIM + col) =
                    make_float2(acc[mi][ni][2] + b0, acc[mi][ni][3] + b1);
            }
        }
    }
}

// Fused Q/K/V projection: blockIdx.z selects weight/output, bf16 hi/lo out
__global__ __launch_bounds__(256) void gemm_qkv(const __nv_bfloat16* __restrict__ xh,
                                                const __nv_bfloat16* __restrict__ xl,
                                                const __nv_bfloat16* __restrict__ wqh,
                                                const __nv_bfloat16* __restrict__ wql,
                                                const __nv_bfloat16* __restrict__ wkh,
                                                const __nv_bfloat16* __restrict__ wkl,
                                                const __nv_bfloat16* __restrict__ wvh,
                                                const __nv_bfloat16* __restrict__ wvl,
                                                __nv_bfloat16* __restrict__ qh,
                                                __nv_bfloat16* __restrict__ ql,
                                                __nv_bfloat16* __restrict__ kh,
                                                __nv_bfloat16* __restrict__ kl,
                                                __nv_bfloat16* __restrict__ vh,
                                                __nv_bfloat16* __restrict__ vl) {
    extern __shared__ char smem[];
    const __nv_bfloat16* bh = (blockIdx.z == 0) ? wqh : (blockIdx.z == 1) ? wkh : wvh;
    const __nv_bfloat16* bl = (blockIdx.z == 0) ? wql : (blockIdx.z == 1) ? wkl : wvl;
    __nv_bfloat16* oh = (blockIdx.z == 0) ? qh : (blockIdx.z == 1) ? kh : vh;
    __nv_bfloat16* ol = (blockIdx.z == 0) ? ql : (blockIdx.z == 1) ? kl : vl;
    gemm_body<true>(xh, xl, bh, bl, nullptr, nullptr, oh, ol,
                    blockIdx.y * 128, blockIdx.x * 128, smem);
}

__global__ __launch_bounds__(256) void gemm_out(const __nv_bfloat16* __restrict__ ah,
                                                const __nv_bfloat16* __restrict__ al,
                                                const __nv_bfloat16* __restrict__ bh,
                                                const __nv_bfloat16* __restrict__ bl,
                                                const float* __restrict__ bias,
                                                float* __restrict__ C) {
    extern __shared__ char smem[];
    gemm_body<false>(ah, al, bh, bl, bias, C, nullptr, nullptr,
                     blockIdx.y * 128, blockIdx.x * 128, smem);
}

// ---------------------------------------------------------------------------
// HMMA windowed flash attention, bf16 hi/lo inputs, cp.async double buffer.
// Block: 128 threads (4 warps), 64 queries, one (b,h). Warp owns 16 q rows.
// Attention tiles: 64 rows x 64 bf16 (128B data), pitch 144B (conflict-free
// ldmatrix: 8 row-addrs stride 144B -> start banks 0,4,...,28).
// smem: Qh Ql + 2 stages x (Kh Kl Vh Vl) = 10 tiles x 9216B = 92160B.
// V kept [key][d]; PV B-fragments via ldmatrix.trans.
// ---------------------------------------------------------------------------
#define APITCH 144                  // bytes per row
#define ATB    (64 * APITCH)        // 9216 bytes per tile
#define ADYN   (10 * ATB)           // 92160

__global__ __launch_bounds__(128) void attn_mma(const __nv_bfloat16* __restrict__ Qh,
                                                const __nv_bfloat16* __restrict__ Ql,
                                                const __nv_bfloat16* __restrict__ Kh,
                                                const __nv_bfloat16* __restrict__ Kl,
                                                const __nv_bfloat16* __restrict__ Vh,
                                                const __nv_bfloat16* __restrict__ Vl,
                                                __nv_bfloat16* __restrict__ ch,
                                                __nv_bfloat16* __restrict__ cl) {
    extern __shared__ char smem[];
    const uint32_t s0 = smem_u32(smem);

    const int qb = blockIdx.x * 64;
    const int h = blockIdx.y;
    const int b = blockIdx.z;
    const int tid = threadIdx.x;
    const int warp = tid >> 5;
    const int lane = tid & 31;

    // ---- issue Q tile loads (bf16 hi/lo, 64 rows x 128B data) ----
    {
        const char* gQh = (const char*)Qh + (((size_t)b * SEQ + qb) * DIM + h * HDIM) * 2;
        const char* gQl = (const char*)Ql + (((size_t)b * SEQ + qb) * DIM + h * HDIM) * 2;
        for (int i = tid; i < 512; i += 128) {
            int r = i >> 3;
            int c = (i & 7) << 4;
            uint32_t dst = s0 + r * APITCH + c;
            size_t src = (size_t)r * (DIM * 2) + c;
            CP_ASYNC16(dst, gQh + src);
            CP_ASYNC16(dst + ATB, gQl + src);
        }
        CP_COMMIT();
    }

    int kstart = qb - (WIN - 1);
    if (kstart < 0) kstart = 0;
    kstart &= ~63;
    const int ntiles = (qb + 63 - kstart) / 64 + 1;

    auto issueKV = [&](int kt, int s) {
        const size_t base = (((size_t)b * SEQ + kt) * DIM + h * HDIM) * 2;
        const char* pKh = (const char*)Kh + base;
        const char* pKl = (const char*)Kl + base;
        const char* pVh = (const char*)Vh + base;
        const char* pVl = (const char*)Vl + base;
        uint32_t sb = s0 + (2 + s * 4) * ATB;
        for (int i = tid; i < 512; i += 128) {
            int r = i >> 3;
            int c = (i & 7) << 4;
            uint32_t dst = sb + r * APITCH + c;
            size_t src = (size_t)r * (DIM * 2) + c;
            CP_ASYNC16(dst,           pKh + src);
            CP_ASYNC16(dst + ATB,     pKl + src);
            CP_ASYNC16(dst + 2 * ATB, pVh + src);
            CP_ASYNC16(dst + 3 * ATB, pVl + src);
        }
    };

    issueKV(kstart, 0);
    CP_COMMIT();
    CP_WAIT(1);   // Q group complete
    __syncthreads();

    // ---- preload Q A-frags ----
    const int a_r = lane & 15, a_c = (lane >> 4) * 8;
    const int b_r = (lane & 7) + ((lane >> 4) & 1) * 8, b_c = ((lane >> 3) & 1) * 8;
    const int v_r = (lane & 7) + ((lane >> 3) & 1) * 8, v_c = ((lane >> 4) & 1) * 8;

    uint32_t qfh[4][4], qfl[4][4];
#pragma unroll
    for (int t = 0; t < 4; t++) {
        uint32_t off = (uint32_t)((warp * 16 + a_r) * APITCH + (t * 16 + a_c) * 2);
        ldsm_x4(qfh[t][0], qfh[t][1], qfh[t][2], qfh[t][3], s0 + off);
        ldsm_x4(qfl[t][0], qfl[t][1], qfl[t][2], qfl[t][3], s0 + ATB + off);
    }

    float m0 = -1e30f, m1 = -1e30f, l0 = 0.0f, l1 = 0.0f;
    float o[8][4];
#pragma unroll
    for (int j = 0; j < 8; j++)
#pragma unroll
        for (int r = 0; r < 4; r++) o[j][r] = 0.0f;

    const int row0 = qb + warp * 16 + (lane >> 2);
    const int row1 = row0 + 8;

    for (int it = 0; it < ntiles; ++it) {
        const int kt = kstart + it * 64;
        const int s = it & 1;
        if (it + 1 < ntiles) {
            issueKV(kt + 64, s ^ 1);
            CP_COMMIT();
            CP_WAIT(1);
        } else {
            CP_WAIT(0);
        }
        __syncthreads();

        const uint32_t sKh = s0 + (2 + s * 4) * ATB;
        const uint32_t sKl = sKh + ATB;
        const uint32_t sVh = sKh + 2 * ATB;
        const uint32_t sVl = sKh + 3 * ATB;

        // ---- scores S = Q K^T (3-pass) ----
        float acc[8][4];
#pragma unroll
        for (int j = 0; j < 8; j++)
#pragma unroll
            for (int r = 0; r < 4; r++) acc[j][r] = 0.0f;

#pragma unroll
        for (int t = 0; t < 4; t++) {
#pragma unroll
            for (int g = 0; g < 4; g++) {
                uint32_t off = (uint32_t)((g * 16 + b_r) * APITCH + (t * 16 + b_c) * 2);
                uint32_t kh0, kh1, kh2, kh3, kl0, kl1, kl2, kl3;
                ldsm_x4(kh0, kh1, kh2, kh3, sKh + off);
                ldsm_x4(kl0, kl1, kl2, kl3, sKl + off);
                int n0 = 2 * g, n1 = 2 * g + 1;
                mma_bf16(acc[n0][0], acc[n0][1], acc[n0][2], acc[n0][3],
                         qfh[t][0], qfh[t][1], qfh[t][2], qfh[t][3], kh0, kh1);
                mma_bf16(acc[n0][0], acc[n0][1], acc[n0][2], acc[n0][3],
                         qfh[t][0], qfh[t][1], qfh[t][2], qfh[t][3], kl0, kl1);
                mma_bf16(acc[n0][0], acc[n0][1], acc[n0][2], acc[n0][3],
                         qfl[t][0], qfl[t][1], qfl[t][2], qfl[t][3], kh0, kh1);
                mma_bf16(acc[n1][0], acc[n1][1], acc[n1][2], acc[n1][3],
                         qfh[t][0], qfh[t][1], qfh[t][2], qfh[t][3], kh2, kh3);
                mma_bf16(acc[n1][0], acc[n1][1], acc[n1][2], acc[n1][3],
                         qfh[t][0], qfh[t][1], qfh[t][2], qfh[t][3], kl2, kl3);
                mma_bf16(acc[n1][0], acc[n1][1], acc[n1][2], acc[n1][3],
                         qfl[t][0], qfl[t][1], qfl[t][2], qfl[t][3], kh2, kh3);
            }
        }

        // ---- mask + online softmax ----
        float tmax0 = -1e30f, tmax1 = -1e30f;
#pragma unroll
        for (int j = 0; j < 8; j++) {
            int colb = kt + 8 * j + 2 * (lane & 3);
#pragma unroll
            for (int e = 0; e < 2; e++) {
                int col = colb + e;
                bool v0 = (col <= row0) && (row0 - col < WIN);
                bool v1 = (col <= row1) && (row1 - col < WIN);
                if (!v0) acc[j][e] = -1e30f;
                if (!v1) acc[j][2 + e] = -1e30f;
            }
            tmax0 = fmaxf(tmax0, fmaxf(acc[j][0], acc[j][1]));
            tmax1 = fmaxf(tmax1, fmaxf(acc[j][2], acc[j][3]));
        }
#pragma unroll
        for (int off = 1; off <= 2; off <<= 1) {
            tmax0 = fmaxf(tmax0, __shfl_xor_sync(0xffffffffu, tmax0, off));
            tmax1 = fmaxf(tmax1, __shfl_xor_sync(0xffffffffu, tmax1, off));
        }
        float mn0 = fmaxf(m0, tmax0);
        float mn1 = fmaxf(m1, tmax1);

        float rs0 = 0.0f, rs1 = 0.0f;
#pragma unroll
        for (int j = 0; j < 8; j++) {
            acc[j][0] = __expf(acc[j][0] - mn0);
            acc[j][1] = __expf(acc[j][1] - mn0);
            acc[j][2] = __expf(acc[j][2] - mn1);
            acc[j][3] = __expf(acc[j][3] - mn1);
            rs0 += acc[j][0] + acc[j][1];
            rs1 += acc[j][2] + acc[j][3];
        }
#pragma unroll
        for (int off = 1; off <= 2; off <<= 1) {
            rs0 += __shfl_xor_sync(0xffffffffu, rs0, off);
            rs1 += __shfl_xor_sync(0xffffffffu, rs1, off);
        }
        float corr0 = __expf(m0 - mn0);
        float corr1 = __expf(m1 - mn1);
        l0 = l0 * corr0 + rs0;
        l1 = l1 * corr1 + rs1;
        m0 = mn0;
        m1 = mn1;
#pragma unroll
        for (int j = 0; j < 8; j++) {
            o[j][0] *= corr0;
            o[j][1] *= corr0;
            o[j][2] *= corr1;
            o[j][3] *= corr1;
        }

        // ---- O += P V (3-pass, P from registers; V via ldmatrix.trans) ----
#pragma unroll
        for (int t = 0; t < 4; t++) {   // key 16-slices
            uint32_t ph[4], pl[4];
            split2(acc[2 * t][0], acc[2 * t][1], ph[0], pl[0]);
            split2(acc[2 * t][2], acc[2 * t][3], ph[1], pl[1]);
            split2(acc[2 * t + 1][0], acc[2 * t + 1][1], ph[2], pl[2]);
            split2(acc[2 * t + 1][2], acc[2 * t + 1][3], ph[3], pl[3]);
#pragma unroll
            for (int g = 0; g < 4; g++) {  // d 16-groups
                uint32_t off = (uint32_t)((t * 16 + v_r) * APITCH + (g * 16 + v_c) * 2);
                uint32_t vh0, vh1, vh2, vh3, vl0, vl1, vl2, vl3;
                ldsm_x4_t(vh0, vh1, vh2, vh3, sVh + off);
                ldsm_x4_t(vl0, vl1, vl2, vl3, sVl + off);
                int n0 = 2 * g, n1 = 2 * g + 1;
                mma_bf16(o[n0][0], o[n0][1], o[n0][2], o[n0][3],
                         ph[0], ph[1], ph[2], ph[3], vh0, vh1);
                mma_bf16(o[n0][0], o[n0][1], o[n0][2], o[n0][3],
                         ph[0], ph[1], ph[2], ph[3], vl0, vl1);
                mma_bf16(o[n0][0], o[n0][1], o[n0][2], o[n0][3],
                         pl[0], pl[1], pl[2], pl[3], vh0, vh1);
                mma_bf16(o[n1][0], o[n1][1], o[n1][2], o[n1][3],
                         ph[0], ph[1], ph[2], ph[3], vh2, vh3);
                mma_bf16(o[n1][0], o[n1][1], o[n1][2], o[n1][3],
                         ph[0], ph[1], ph[2], ph[3], vl2, vl3);
                mma_bf16(o[n1][0], o[n1][1], o[n1][2], o[n1][3],
                         pl[0], pl[1], pl[2], pl[3], vh2, vh3);
            }
        }
        __syncthreads();   // all reads of this stage done before it is overwritten
    }

    // ---- epilogue: normalize, split to bf16 hi/lo ctx ----
    float inv0 = 1.0f / l0;
    float inv1 = 1.0f / l1;
    const size_t tok0 = (size_t)b * SEQ + row0;
    const size_t tok1 = (size_t)b * SEQ + row1;
    const int colbase = h * HDIM + 2 * (lane & 3);
#pragma unroll
    for (int j = 0; j < 8; j++) {
        int col = colbase + 8 * j;
        uint32_t h0, lo0, h1, lo1;
        split2(o[j][0] * inv0, o[j][1] * inv0, h0, lo0);
        split2(o[j][2] * inv1, o[j][3] * inv1, h1, lo1);
        *(uint32_t*)(ch + tok0 * DIM + col) = h0;
        *(uint32_t*)(cl + tok0 * DIM + col) = lo0;
        *(uint32_t*)(ch + tok1 * DIM + col) = h1;
        *(uint32_t*)(cl + tok1 * DIM + col) = lo1;
    }
}

// ---------------------------------------------------------------------------
extern "C" void kernel_launch(void* const* d_in, const int* in_sizes, int n_in,
                              void* d_out, int out_size) {
    (void)in_sizes; (void)n_in; (void)out_size;
    const float* X  = (const float*)d_in[0];
    const float* Wq = (const float*)d_in[1];
    const float* Wk = (const float*)d_in[2];
    const float* Wv = (const float*)d_in[3];
    const float* Wo = (const float*)d_in[4];
    const float* bo = (const float*)d_in[5];
    float* out = (float*)d_out;

    __nv_bfloat16 *qh, *ql, *kh, *kl, *vh, *vl, *xh, *xl, *ch, *cl;
    __nv_bfloat16 *wqh, *wql, *wkh, *wkl, *wvh, *wvl, *woh, *wol;
    cudaGetSymbolAddress((void**)&qh, g_qh);
    cudaGetSymbolAddress((void**)&ql, g_ql);
    cudaGetSymbolAddress((void**)&kh, g_kh);
    cudaGetSymbolAddress((void**)&kl, g_kl);
    cudaGetSymbolAddress((void**)&vh, g_vh);
    cudaGetSymbolAddress((void**)&vl, g_vl);
    cudaGetSymbolAddress((void**)&xh, g_xh);
    cudaGetSymbolAddress((void**)&xl, g_xl);
    cudaGetSymbolAddress((void**)&ch, g_ch);
    cudaGetSymbolAddress((void**)&cl, g_cl);
    cudaGetSymbolAddress((void**)&wqh, g_wqh);
    cudaGetSymbolAddress((void**)&wql, g_wql);
    cudaGetSymbolAddress((void**)&wkh, g_wkh);
    cudaGetSymbolAddress((void**)&wkl, g_wkl);
    cudaGetSymbolAddress((void**)&wvh, g_wvh);
    cudaGetSymbolAddress((void**)&wvl, g_wvl);
    cudaGetSymbolAddress((void**)&woh, g_woh);
    cudaGetSymbolAddress((void**)&wol, g_wol);

    const int DYN = 2 * STAGEB;
    cudaFuncSetAttribute(gemm_qkv, cudaFuncAttributeMaxDynamicSharedMemorySize, DYN);
    cudaFuncSetAttribute(gemm_out, cudaFuncAttributeMaxDynamicSharedMemorySize, DYN);
    cudaFuncSetAttribute(attn_mma, cudaFuncAttributeMaxDynamicSharedMemorySize, ADYN);

    const int nX = MROWS * DIM;
    const int nW = DIM * DIM;

    split_bf16<<<nX / 1024, 256>>>(X, xh, xl, nX);
    split_bf16<<<nW / 1024, 256>>>(Wq, wqh, wql, nW);
    split_bf16<<<nW / 1024, 256>>>(Wk, wkh, wkl, nW);
    split_bf16<<<nW / 1024, 256>>>(Wv, wvh, wvl, nW);
    split_bf16<<<nW / 1024, 256>>>(Wo, woh, wol, nW);

    dim3 qkv_grid(DIM / 128, MROWS / 128, 3);
    gemm_qkv<<<qkv_grid, 256, DYN>>>(xh, xl, wqh, wql, wkh, wkl, wvh, wvl,
                                     qh, ql, kh, kl, vh, vl);

    dim3 attn_grid(SEQ / 64, NHEAD, BATCH);
    attn_mma<<<attn_grid, 128, ADYN>>>(qh, ql, kh, kl, vh, vl, ch, cl);

    dim3 ogrid(DIM / 128, MROWS / 128);
    gemm_out<<<ogrid, 256, DYN>>>(ch, cl, woh, wol, bo, out);
}

// round 7
// speedup vs baseline: 3.5342x; 1.0236x over previous
#include <cuda_runtime.h>
#include <cuda_bf16.h>
#include <stdint.h>

// Problem constants
#define BATCH 4
#define SEQ   2048
#define DIM   1024
#define NHEAD 16
#define HDIM  64
#define WIN   256
#define MROWS (BATCH * SEQ)   // 8192

// ---------------------------------------------------------------------------
// Scratch (device globals: allocation-free rule)
// ---------------------------------------------------------------------------
__device__ __nv_bfloat16 g_qh[MROWS * DIM];
__device__ __nv_bfloat16 g_ql[MROWS * DIM];
__device__ __nv_bfloat16 g_kh[MROWS * DIM];
__device__ __nv_bfloat16 g_kl[MROWS * DIM];
__device__ __nv_bfloat16 g_vh[MROWS * DIM];
__device__ __nv_bfloat16 g_vl[MROWS * DIM];
__device__ __nv_bfloat16 g_xh[MROWS * DIM];
__device__ __nv_bfloat16 g_xl[MROWS * DIM];
__device__ __nv_bfloat16 g_ch[MROWS * DIM];
__device__ __nv_bfloat16 g_cl[MROWS * DIM];
__device__ __nv_bfloat16 g_wqh[DIM * DIM];
__device__ __nv_bfloat16 g_wql[DIM * DIM];
__device__ __nv_bfloat16 g_wkh[DIM * DIM];
__device__ __nv_bfloat16 g_wkl[DIM * DIM];
__device__ __nv_bfloat16 g_wvh[DIM * DIM];
__device__ __nv_bfloat16 g_wvl[DIM * DIM];
__device__ __nv_bfloat16 g_woh[DIM * DIM];
__device__ __nv_bfloat16 g_wol[DIM * DIM];

// ---------------------------------------------------------------------------
// Portable PTX helpers
// ---------------------------------------------------------------------------
__device__ __forceinline__ uint32_t smem_u32(const void* p) {
    uint32_t a;
    asm("{ .reg .u64 t; cvta.to.shared.u64 t, %1; cvt.u32.u64 %0, t; }"
        : "=r"(a) : "l"(p));
    return a;
}

#define CP_ASYNC16(dst, src) \
    asm volatile("cp.async.cg.shared.global [%0], [%1], 16;" :: "r"(dst), "l"(src))
#define CP_COMMIT() asm volatile("cp.async.commit_group;" ::: "memory")
#define CP_WAIT(n)  asm volatile("cp.async.wait_group %0;" :: "n"(n) : "memory")

__device__ __forceinline__ void ldsm_x4(uint32_t& r0, uint32_t& r1,
                                        uint32_t& r2, uint32_t& r3, uint32_t addr) {
    asm volatile("ldmatrix.sync.aligned.m8n8.x4.shared.b16 {%0,%1,%2,%3}, [%4];"
                 : "=r"(r0), "=r"(r1), "=r"(r2), "=r"(r3) : "r"(addr));
}

__device__ __forceinline__ void ldsm_x4_t(uint32_t& r0, uint32_t& r1,
                                          uint32_t& r2, uint32_t& r3, uint32_t addr) {
    asm volatile("ldmatrix.sync.aligned.m8n8.x4.trans.shared.b16 {%0,%1,%2,%3}, [%4];"
                 : "=r"(r0), "=r"(r1), "=r"(r2), "=r"(r3) : "r"(addr));
}

__device__ __forceinline__ void mma_bf16(float& c0, float& c1, float& c2, float& c3,
                                         uint32_t a0, uint32_t a1, uint32_t a2, uint32_t a3,
                                         uint32_t b0, uint32_t b1) {
    asm volatile(
        "mma.sync.aligned.m16n8k16.row.col.f32.bf16.bf16.f32 "
        "{%0,%1,%2,%3}, {%4,%5,%6,%7}, {%8,%9}, {%0,%1,%2,%3};"
        : "+f"(c0), "+f"(c1), "+f"(c2), "+f"(c3)
        : "r"(a0), "r"(a1), "r"(a2), "r"(a3), "r"(b0), "r"(b1));
}

__device__ __forceinline__ uint32_t pack_bf2(__nv_bfloat16 a, __nv_bfloat16 b) {
    __nv_bfloat162 t(a, b);
    return *(uint32_t*)&t;
}

__device__ __forceinline__ void split2(float a, float b, uint32_t& hi, uint32_t& lo) {
    __nv_bfloat16 ha = __float2bfloat16(a), hb = __float2bfloat16(b);
    float ra = a - __bfloat162float(ha);
    float rb = b - __bfloat162float(hb);
    hi = pack_bf2(ha, hb);
    lo = pack_bf2(__float2bfloat16(ra), __float2bfloat16(rb));
}

// ---------------------------------------------------------------------------
// fp32 -> bf16 hi/lo splits
// ---------------------------------------------------------------------------
__global__ __launch_bounds__(256) void split_bf16(const float* __restrict__ src,
                                                  __nv_bfloat16* __restrict__ hi,
                                                  __nv_bfloat16* __restrict__ lo,
                                                  int n) {
    int i = (blockIdx.x * 256 + threadIdx.x) * 4;
    if (i >= n) return;
    float4 x = *(const float4*)(src + i);
    uint32_t h0, l0, h1, l1;
    split2(x.x, x.y, h0, l0);
    split2(x.z, x.w, h1, l1);
    uint32_t* ph = (uint32_t*)(hi + i);
    uint32_t* pl = (uint32_t*)(lo + i);
    ph[0] = h0; ph[1] = h1;
    pl[0] = l0; pl[1] = l1;
}

// all 4 weight matrices in one launch; blockIdx.y selects the tensor
__global__ __launch_bounds__(256) void split_w4(const float* __restrict__ s0,
                                                const float* __restrict__ s1,
                                                const float* __restrict__ s2,
                                                const float* __restrict__ s3,
                                                __nv_bfloat16* __restrict__ h0,
                                                __nv_bfloat16* __restrict__ l0p,
                                                __nv_bfloat16* __restrict__ h1,
                                                __nv_bfloat16* __restrict__ l1p,
                                                __nv_bfloat16* __restrict__ h2,
                                                __nv_bfloat16* __restrict__ l2p,
                                                __nv_bfloat16* __restrict__ h3,
                                                __nv_bfloat16* __restrict__ l3p) {
    int w = blockIdx.y;
    const float* src = (w == 0) ? s0 : (w == 1) ? s1 : (w == 2) ? s2 : s3;
    __nv_bfloat16* hi = (w == 0) ? h0 : (w == 1) ? h1 : (w == 2) ? h2 : h3;
    __nv_bfloat16* lo = (w == 0) ? l0p : (w == 1) ? l1p : (w == 2) ? l2p : l3p;
    int i = (blockIdx.x * 256 + threadIdx.x) * 4;
    float4 x = *(const float4*)(src + i);
    uint32_t a0, b0, a1, b1;
    split2(x.x, x.y, a0, b0);
    split2(x.z, x.w, a1, b1);
    uint32_t* ph = (uint32_t*)(hi + i);
    uint32_t* pl = (uint32_t*)(lo + i);
    ph[0] = a0; ph[1] = a1;
    pl[0] = b0; pl[1] = b1;
}

// ---------------------------------------------------------------------------
// HMMA bf16-split GEMM core (fragment maps verified R3/R4)
// ---------------------------------------------------------------------------
#define GP      40
#define TBYTES  (128 * GP * 2)
#define STAGEB  (4 * TBYTES)
#define NCH     (DIM / 32)

template <bool BF16OUT>
__device__ __forceinline__ void gemm_body(const __nv_bfloat16* Ah, const __nv_bfloat16* Al,
                                          const __nv_bfloat16* Bh, const __nv_bfloat16* Bl,
                                          const float* bias, float* C,
                                          __nv_bfloat16* Ch, __nv_bfloat16* Cl,
                                          int bm, int bn, char* smem) {
    const int tid = threadIdx.x;
    const int wid = tid >> 5;
    const int lane = tid & 31;
    const int wm = (wid & 1) * 64;
    const int wn = (wid >> 1) * 32;
    const uint32_t sbase = smem_u32(smem);

    const char* gAh = (const char*)Ah + (size_t)bm * (DIM * 2);
    const char* gAl = (const char*)Al + (size_t)bm * (DIM * 2);
    const char* gBh = (const char*)Bh + (size_t)bn * (DIM * 2);
    const char* gBl = (const char*)Bl + (size_t)bn * (DIM * 2);

    auto issue = [&](int c, int s) {
        char* st = smem + s * STAGEB;
        const size_t gk = (size_t)c * 64;
#pragma unroll
        for (int rep = 0; rep < 2; rep++) {
            int t = rep ? (tid + 256) : tid;
            int r = t >> 2;
            int cc = (t & 3) << 4;
            uint32_t dst = smem_u32(st) + r * 80 + cc;
            size_t src = (size_t)r * (DIM * 2) + gk + cc;
            CP_ASYNC16(dst,              gAh + src);
            CP_ASYNC16(dst + TBYTES,     gAl + src);
            CP_ASYNC16(dst + 2 * TBYTES, gBh + src);
            CP_ASYNC16(dst + 3 * TBYTES, gBl + src);
        }
    };

    float acc[4][4][4];
#pragma unroll
    for (int i = 0; i < 4; i++)
#pragma unroll
        for (int j = 0; j < 4; j++)
#pragma unroll
            for (int r = 0; r < 4; r++) acc[i][j][r] = 0.0f;

    const int a_r = lane & 15, a_c = (lane >> 4) * 8;
    const int b_r = (lane & 7) + ((lane >> 4) & 1) * 8, b_c = ((lane >> 3) & 1) * 8;

    issue(0, 0);
    CP_COMMIT();

    for (int c = 0; c < NCH; ++c) {
        const int s = c & 1;
        if (c + 1 < NCH) {
            issue(c + 1, s ^ 1);
            CP_COMMIT();
            CP_WAIT(1);
        } else {
            CP_WAIT(0);
        }
        __syncthreads();

        const uint32_t st = sbase + s * STAGEB;
        const uint32_t pAh = st;
        const uint32_t pAl = st + TBYTES;
        const uint32_t pBh = st + 2 * TBYTES;
        const uint32_t pBl = st + 3 * TBYTES;

#pragma unroll
        for (int kk = 0; kk < 32; kk += 16) {
            uint32_t ah[4][4], al[4][4];
#pragma unroll
            for (int mi = 0; mi < 4; mi++) {
                uint32_t off = (uint32_t)((wm + mi * 16 + a_r) * 80 + (kk + a_c) * 2);
                ldsm_x4(ah[mi][0], ah[mi][1], ah[mi][2], ah[mi][3], pAh + off);
                ldsm_x4(al[mi][0], al[mi][1], al[mi][2], al[mi][3], pAl + off);
            }
            uint32_t bh[4][2], bl[4][2];
#pragma unroll
            for (int nb = 0; nb < 2; nb++) {
                uint32_t off = (uint32_t)((wn + nb * 16 + b_r) * 80 + (kk + b_c) * 2);
                uint32_t r0, r1, r2, r3;
                ldsm_x4(r0, r1, r2, r3, pBh + off);
                bh[nb * 2][0] = r0; bh[nb * 2][1] = r1;
                bh[nb * 2 + 1][0] = r2; bh[nb * 2 + 1][1] = r3;
                ldsm_x4(r0, r1, r2, r3, pBl + off);
                bl[nb * 2][0] = r0; bl[nb * 2][1] = r1;
                bl[nb * 2 + 1][0] = r2; bl[nb * 2 + 1][1] = r3;
            }
#pragma unroll
            for (int mi = 0; mi < 4; mi++)
#pragma unroll
                for (int ni = 0; ni < 4; ni++) {
                    mma_bf16(acc[mi][ni][0], acc[mi][ni][1], acc[mi][ni][2], acc[mi][ni][3],
                             ah[mi][0], ah[mi][1], ah[mi][2], ah[mi][3],
                             bh[ni][0], bh[ni][1]);
                    mma_bf16(acc[mi][ni][0], acc[mi][ni][1], acc[mi][ni][2], acc[mi][ni][3],
                             ah[mi][0], ah[mi][1], ah[mi][2], ah[mi][3],
                             bl[ni][0], bl[ni][1]);
                    mma_bf16(acc[mi][ni][0], acc[mi][ni][1], acc[mi][ni][2], acc[mi][ni][3],
                             al[mi][0], al[mi][1], al[mi][2], al[mi][3],
                             bh[ni][0], bh[ni][1]);
                }
        }
        __syncthreads();
    }

    const int er = lane >> 2;
    const int ec = (lane & 3) * 2;
#pragma unroll
    for (int mi = 0; mi < 4; mi++) {
#pragma unroll
        for (int ni = 0; ni < 4; ni++) {
            int col = bn + wn + ni * 8 + ec;
            int row0 = bm + wm + mi * 16 + er;
            int row1 = row0 + 8;
            if (BF16OUT) {
                uint32_t h0, l0, h1, l1;
                split2(acc[mi][ni][0], acc[mi][ni][1], h0, l0);
                split2(acc[mi][ni][2], acc[mi][ni][3], h1, l1);
                *(uint32_t*)(Ch + (size_t)row0 * DIM + col) = h0;
                *(uint32_t*)(Cl + (size_t)row0 * DIM + col) = l0;
                *(uint32_t*)(Ch + (size_t)row1 * DIM + col) = h1;
                *(uint32_t*)(Cl + (size_t)row1 * DIM + col) = l1;
            } else {
                float b0 = bias[col], b1 = bias[col + 1];
                *(float2*)(C + (size_t)row0 * DIM + col) =
                    make_float2(acc[mi][ni][0] + b0, acc[mi][ni][1] + b1);
                *(float2*)(C + (size_t)row1 * DIM + col) =
                    make_float2(acc[mi][ni][2] + b0, acc[mi][ni][3] + b1);
            }
        }
    }
}

__global__ __launch_bounds__(256) void gemm_qkv(const __nv_bfloat16* __restrict__ xh,
                                                const __nv_bfloat16* __restrict__ xl,
                                                const __nv_bfloat16* __restrict__ wqh,
                                                const __nv_bfloat16* __restrict__ wql,
                                                const __nv_bfloat16* __restrict__ wkh,
                                                const __nv_bfloat16* __restrict__ wkl,
                                                const __nv_bfloat16* __restrict__ wvh,
                                                const __nv_bfloat16* __restrict__ wvl,
                                                __nv_bfloat16* __restrict__ qh,
                                                __nv_bfloat16* __restrict__ ql,
                                                __nv_bfloat16* __restrict__ kh,
                                                __nv_bfloat16* __restrict__ kl,
                                                __nv_bfloat16* __restrict__ vh,
                                                __nv_bfloat16* __restrict__ vl) {
    extern __shared__ char smem[];
    const __nv_bfloat16* bh = (blockIdx.z == 0) ? wqh : (blockIdx.z == 1) ? wkh : wvh;
    const __nv_bfloat16* bl = (blockIdx.z == 0) ? wql : (blockIdx.z == 1) ? wkl : wvl;
    __nv_bfloat16* oh = (blockIdx.z == 0) ? qh : (blockIdx.z == 1) ? kh : vh;
    __nv_bfloat16* ol = (blockIdx.z == 0) ? ql : (blockIdx.z == 1) ? kl : vl;
    gemm_body<true>(xh, xl, bh, bl, nullptr, nullptr, oh, ol,
                    blockIdx.y * 128, blockIdx.x * 128, smem);
}

__global__ __launch_bounds__(256) void gemm_out(const __nv_bfloat16* __restrict__ ah,
                                                const __nv_bfloat16* __restrict__ al,
                                                const __nv_bfloat16* __restrict__ bh,
                                                const __nv_bfloat16* __restrict__ bl,
                                                const float* __restrict__ bias,
                                                float* __restrict__ C) {
    extern __shared__ char smem[];
    gemm_body<false>(ah, al, bh, bl, bias, C, nullptr, nullptr,
                     blockIdx.y * 128, blockIdx.x * 128, smem);
}

// ---------------------------------------------------------------------------
// HMMA windowed flash attention, bf16 hi/lo inputs.
// Block: 128 threads (4 warps), 64 queries. Tiles 64 rows x 128B, pitch 144B.
// smem arena: 8 tiles (73728B). Q uses tiles 0-1 only during fragment preload,
// then the same space becomes KV double-buffer stage 0 (tiles 0-3) / stage 1
// (tiles 4-7). 3 CTAs/SM.
// ---------------------------------------------------------------------------
#define APITCH 144
#define ATB    (64 * APITCH)        // 9216 bytes per tile
#define ADYN   (8 * ATB)            // 73728

__global__ __launch_bounds__(128, 3) void attn_mma(const __nv_bfloat16* __restrict__ Qh,
                                                   const __nv_bfloat16* __restrict__ Ql,
                                                   const __nv_bfloat16* __restrict__ Kh,
                                                   const __nv_bfloat16* __restrict__ Kl,
                                                   const __nv_bfloat16* __restrict__ Vh,
                                                   const __nv_bfloat16* __restrict__ Vl,
                                                   __nv_bfloat16* __restrict__ ch,
                                                   __nv_bfloat16* __restrict__ cl) {
    extern __shared__ char smem[];
    const uint32_t s0 = smem_u32(smem);

    const int qb = blockIdx.x * 64;
    const int h = blockIdx.y;
    const int b = blockIdx.z;
    const int tid = threadIdx.x;
    const int warp = tid >> 5;
    const int lane = tid & 31;

    // ---- Phase 1: Q tile -> smem tiles 0,1 -> register fragments ----
    {
        const char* gQh = (const char*)Qh + (((size_t)b * SEQ + qb) * DIM + h * HDIM) * 2;
        const char* gQl = (const char*)Ql + (((size_t)b * SEQ + qb) * DIM + h * HDIM) * 2;
        for (int i = tid; i < 512; i += 128) {
            int r = i >> 3;
            int c = (i & 7) << 4;
            uint32_t dst = s0 + r * APITCH + c;
            size_t src = (size_t)r * (DIM * 2) + c;
            CP_ASYNC16(dst, gQh + src);
            CP_ASYNC16(dst + ATB, gQl + src);
        }
        CP_COMMIT();
        CP_WAIT(0);
        __syncthreads();
    }

    const int a_r = lane & 15, a_c = (lane >> 4) * 8;
    const int b_r = (lane & 7) + ((lane >> 4) & 1) * 8, b_c = ((lane >> 3) & 1) * 8;
    const int v_r = (lane & 7) + ((lane >> 3) & 1) * 8, v_c = ((lane >> 4) & 1) * 8;

    uint32_t qfh[4][4], qfl[4][4];
#pragma unroll
    for (int t = 0; t < 4; t++) {
        uint32_t off = (uint32_t)((warp * 16 + a_r) * APITCH + (t * 16 + a_c) * 2);
        ldsm_x4(qfh[t][0], qfh[t][1], qfh[t][2], qfh[t][3], s0 + off);
        ldsm_x4(qfl[t][0], qfl[t][1], qfl[t][2], qfl[t][3], s0 + ATB + off);
    }
    __syncthreads();   // Q smem fully consumed; arena now belongs to the KV pipeline

    // ---- Phase 2: KV double-buffered mainloop ----
    int kstart = qb - (WIN - 1);
    if (kstart < 0) kstart = 0;
    kstart &= ~63;
    const int ntiles = (qb + 63 - kstart) / 64 + 1;

    auto issueKV = [&](int kt, int s) {
        const size_t base = (((size_t)b * SEQ + kt) * DIM + h * HDIM) * 2;
        const char* pKh = (const char*)Kh + base;
        const char* pKl = (const char*)Kl + base;
        const char* pVh = (const char*)Vh + base;
        const char* pVl = (const char*)Vl + base;
        uint32_t sb = s0 + s * 4 * ATB;
        for (int i = tid; i < 512; i += 128) {
            int r = i >> 3;
            int c = (i & 7) << 4;
            uint32_t dst = sb + r * APITCH + c;
            size_t src = (size_t)r * (DIM * 2) + c;
            CP_ASYNC16(dst,           pKh + src);
            CP_ASYNC16(dst + ATB,     pKl + src);
            CP_ASYNC16(dst + 2 * ATB, pVh + src);
            CP_ASYNC16(dst + 3 * ATB, pVl + src);
        }
    };

    issueKV(kstart, 0);
    CP_COMMIT();
    if (ntiles > 1) {
        issueKV(kstart + 64, 1);
        CP_COMMIT();
    }

    float m0 = -1e30f, m1 = -1e30f, l0 = 0.0f, l1 = 0.0f;
    float o[8][4];
#pragma unroll
    for (int j = 0; j < 8; j++)
#pragma unroll
        for (int r = 0; r < 4; r++) o[j][r] = 0.0f;

    const int row0 = qb + warp * 16 + (lane >> 2);
    const int row1 = row0 + 8;

    for (int it = 0; it < ntiles; ++it) {
        const int kt = kstart + it * 64;
        const int s = it & 1;
        if (it + 1 < ntiles) { CP_WAIT(1); } else { CP_WAIT(0); }
        __syncthreads();

        const uint32_t sKh = s0 + s * 4 * ATB;
        const uint32_t sKl = sKh + ATB;
        const uint32_t sVh = sKh + 2 * ATB;
        const uint32_t sVl = sKh + 3 * ATB;

        // ---- scores S = Q K^T (3-pass) ----
        float acc[8][4];
#pragma unroll
        for (int j = 0; j < 8; j++)
#pragma unroll
            for (int r = 0; r < 4; r++) acc[j][r] = 0.0f;

#pragma unroll
        for (int t = 0; t < 4; t++) {
#pragma unroll
            for (int g = 0; g < 4; g++) {
                uint32_t off = (uint32_t)((g * 16 + b_r) * APITCH + (t * 16 + b_c) * 2);
                uint32_t kh0, kh1, kh2, kh3, kl0, kl1, kl2, kl3;
                ldsm_x4(kh0, kh1, kh2, kh3, sKh + off);
                ldsm_x4(kl0, kl1, kl2, kl3, sKl + off);
                int n0 = 2 * g, n1 = 2 * g + 1;
                mma_bf16(acc[n0][0], acc[n0][1], acc[n0][2], acc[n0][3],
                         qfh[t][0], qfh[t][1], qfh[t][2], qfh[t][3], kh0, kh1);
                mma_bf16(acc[n1][0], acc[n1][1], acc[n1][2], acc[n1][3],
                         qfh[t][0], qfh[t][1], qfh[t][2], qfh[t][3], kh2, kh3);
                mma_bf16(acc[n0][0], acc[n0][1], acc[n0][2], acc[n0][3],
                         qfh[t][0], qfh[t][1], qfh[t][2], qfh[t][3], kl0, kl1);
                mma_bf16(acc[n1][0], acc[n1][1], acc[n1][2], acc[n1][3],
                         qfh[t][0], qfh[t][1], qfh[t][2], qfh[t][3], kl2, kl3);
                mma_bf16(acc[n0][0], acc[n0][1], acc[n0][2], acc[n0][3],
                         qfl[t][0], qfl[t][1], qfl[t][2], qfl[t][3], kh0, kh1);
                mma_bf16(acc[n1][0], acc[n1][1], acc[n1][2], acc[n1][3],
                         qfl[t][0], qfl[t][1], qfl[t][2], qfl[t][3], kh2, kh3);
            }
        }

        // ---- mask + online softmax ----
        float tmax0 = -1e30f, tmax1 = -1e30f;
#pragma unroll
        for (int j = 0; j < 8; j++) {
            int colb = kt + 8 * j + 2 * (lane & 3);
#pragma unroll
            for (int e = 0; e < 2; e++) {
                int col = colb + e;
                bool v0 = (col <= row0) && (row0 - col < WIN);
                bool v1 = (col <= row1) && (row1 - col < WIN);
                if (!v0) acc[j][e] = -1e30f;
                if (!v1) acc[j][2 + e] = -1e30f;
            }
            tmax0 = fmaxf(tmax0, fmaxf(acc[j][0], acc[j][1]));
            tmax1 = fmaxf(tmax1, fmaxf(acc[j][2], acc[j][3]));
        }
#pragma unroll
        for (int off = 1; off <= 2; off <<= 1) {
            tmax0 = fmaxf(tmax0, __shfl_xor_sync(0xffffffffu, tmax0, off));
            tmax1 = fmaxf(tmax1, __shfl_xor_sync(0xffffffffu, tmax1, off));
        }
        float mn0 = fmaxf(m0, tmax0);
        float mn1 = fmaxf(m1, tmax1);

        float rs0 = 0.0f, rs1 = 0.0f;
#pragma unroll
        for (int j = 0; j < 8; j++) {
            acc[j][0] = __expf(acc[j][0] - mn0);
            acc[j][1] = __expf(acc[j][1] - mn0);
            acc[j][2] = __expf(acc[j][2] - mn1);
            acc[j][3] = __expf(acc[j][3] - mn1);
            rs0 += acc[j][0] + acc[j][1];
            rs1 += acc[j][2] + acc[j][3];
        }
#pragma unroll
        for (int off = 1; off <= 2; off <<= 1) {
            rs0 += __shfl_xor_sync(0xffffffffu, rs0, off);
            rs1 += __shfl_xor_sync(0xffffffffu, rs1, off);
        }
        float corr0 = __expf(m0 - mn0);
        float corr1 = __expf(m1 - mn1);
        l0 = l0 * corr0 + rs0;
        l1 = l1 * corr1 + rs1;
        m0 = mn0;
        m1 = mn1;
#pragma unroll
        for (int j = 0; j < 8; j++) {
            o[j][0] *= corr0;
            o[j][1] *= corr0;
            o[j][2] *= corr1;
            o[j][3] *= corr1;
        }

        // ---- O += P V (3-pass, P from registers; V via ldmatrix.trans) ----
#pragma unroll
        for (int t = 0; t < 4; t++) {
            uint32_t ph[4], pl[4];
            split2(acc[2 * t][0], acc[2 * t][1], ph[0], pl[0]);
            split2(acc[2 * t][2], acc[2 * t][3], ph[1], pl[1]);
            split2(acc[2 * t + 1][0], acc[2 * t + 1][1], ph[2], pl[2]);
            split2(acc[2 * t + 1][2], acc[2 * t + 1][3], ph[3], pl[3]);
#pragma unroll
            for (int g = 0; g < 4; g++) {
                uint32_t off = (uint32_t)((t * 16 + v_r) * APITCH + (g * 16 + v_c) * 2);
                uint32_t vh0, vh1, vh2, vh3, vl0, vl1, vl2, vl3;
                ldsm_x4_t(vh0, vh1, vh2, vh3, sVh + off);
                ldsm_x4_t(vl0, vl1, vl2, vl3, sVl + off);
                int n0 = 2 * g, n1 = 2 * g + 1;
                mma_bf16(o[n0][0], o[n0][1], o[n0][2], o[n0][3],
                         ph[0], ph[1], ph[2], ph[3], vh0, vh1);
                mma_bf16(o[n1][0], o[n1][1], o[n1][2], o[n1][3],
                         ph[0], ph[1], ph[2], ph[3], vh2, vh3);
                mma_bf16(o[n0][0], o[n0][1], o[n0][2], o[n0][3],
                         ph[0], ph[1], ph[2], ph[3], vl0, vl1);
                mma_bf16(o[n1][0], o[n1][1], o[n1][2], o[n1][3],
                         ph[0], ph[1], ph[2], ph[3], vl2, vl3);
                mma_bf16(o[n0][0], o[n0][1], o[n0][2], o[n0][3],
                         pl[0], pl[1], pl[2], pl[3], vh0, vh1);
                mma_bf16(o[n1][0], o[n1][1], o[n1][2], o[n1][3],
                         pl[0], pl[1], pl[2], pl[3], vh2, vh3);
            }
        }
        __syncthreads();   // stage s fully read
        if (it + 2 < ntiles) {
            issueKV(kstart + (it + 2) * 64, s);
            CP_COMMIT();
        }
    }

    // ---- epilogue: normalize, split to bf16 hi/lo ctx ----
    float inv0 = 1.0f / l0;
    float inv1 = 1.0f / l1;
    const size_t tok0 = (size_t)b * SEQ + row0;
    const size_t tok1 = (size_t)b * SEQ + row1;
    const int colbase = h * HDIM + 2 * (lane & 3);
#pragma unroll
    for (int j = 0; j < 8; j++) {
        int col = colbase + 8 * j;
        uint32_t h0, lo0, h1, lo1;
        split2(o[j][0] * inv0, o[j][1] * inv0, h0, lo0);
        split2(o[j][2] * inv1, o[j][3] * inv1, h1, lo1);
        *(uint32_t*)(ch + tok0 * DIM + col) = h0;
        *(uint32_t*)(cl + tok0 * DIM + col) = lo0;
        *(uint32_t*)(ch + tok1 * DIM + col) = h1;
        *(uint32_t*)(cl + tok1 * DIM + col) = lo1;
    }
}

// ---------------------------------------------------------------------------
extern "C" void kernel_launch(void* const* d_in, const int* in_sizes, int n_in,
                              void* d_out, int out_size) {
    (void)in_sizes; (void)n_in; (void)out_size;
    const float* X  = (const float*)d_in[0];
    const float* Wq = (const float*)d_in[1];
    const float* Wk = (const float*)d_in[2];
    const float* Wv = (const float*)d_in[3];
    const float* Wo = (const float*)d_in[4];
    const float* bo = (const float*)d_in[5];
    float* out = (float*)d_out;

    __nv_bfloat16 *qh, *ql, *kh, *kl, *vh, *vl, *xh, *xl, *ch, *cl;
    __nv_bfloat16 *wqh, *wql, *wkh, *wkl, *wvh, *wvl, *woh, *wol;
    cudaGetSymbolAddress((void**)&qh, g_qh);
    cudaGetSymbolAddress((void**)&ql, g_ql);
    cudaGetSymbolAddress((void**)&kh, g_kh);
    cudaGetSymbolAddress((void**)&kl, g_kl);
    cudaGetSymbolAddress((void**)&vh, g_vh);
    cudaGetSymbolAddress((void**)&vl, g_vl);
    cudaGetSymbolAddress((void**)&xh, g_xh);
    cudaGetSymbolAddress((void**)&xl, g_xl);
    cudaGetSymbolAddress((void**)&ch, g_ch);
    cudaGetSymbolAddress((void**)&cl, g_cl);
    cudaGetSymbolAddress((void**)&wqh, g_wqh);
    cudaGetSymbolAddress((void**)&wql, g_wql);
    cudaGetSymbolAddress((void**)&wkh, g_wkh);
    cudaGetSymbolAddress((void**)&wkl, g_wkl);
    cudaGetSymbolAddress((void**)&wvh, g_wvh);
    cudaGetSymbolAddress((void**)&wvl, g_wvl);
    cudaGetSymbolAddress((void**)&woh, g_woh);
    cudaGetSymbolAddress((void**)&wol, g_wol);

    const int DYN = 2 * STAGEB;
    cudaFuncSetAttribute(gemm_qkv, cudaFuncAttributeMaxDynamicSharedMemorySize, DYN);
    cudaFuncSetAttribute(gemm_out, cudaFuncAttributeMaxDynamicSharedMemorySize, DYN);
    cudaFuncSetAttribute(attn_mma, cudaFuncAttributeMaxDynamicSharedMemorySize, ADYN);

    const int nX = MROWS * DIM;
    const int nW = DIM * DIM;

    split_bf16<<<nX / 1024, 256>>>(X, xh, xl, nX);
    dim3 wgrid(nW / 1024, 4);
    split_w4<<<wgrid, 256>>>(Wq, Wk, Wv, Wo,
                             wqh, wql, wkh, wkl, wvh, wvl, woh, wol);

    dim3 qkv_grid(DIM / 128, MROWS / 128, 3);
    gemm_qkv<<<qkv_grid, 256, DYN>>>(xh, xl, wqh, wql, wkh, wkl, wvh, wvl,
                                     qh, ql, kh, kl, vh, vl);

    dim3 attn_grid(SEQ / 64, NHEAD, BATCH);
    attn_mma<<<attn_grid, 128, ADYN>>>(qh, ql, kh, kl, vh, vl, ch, cl);

    dim3 ogrid(DIM / 128, MROWS / 128);
    gemm_out<<<ogrid, 256, DYN>>>(ch, cl, woh, wol, bo, out);
}